// round 8
// baseline (speedup 1.0000x reference)
#include <cuda_runtime.h>
#include <cstdint>
#include <math.h>

#define BMAX 2048
__device__ float g_buf0[BMAX * 10 * 4 * 26 * 26];
__device__ float g_buf1[BMAX * 10 * 4 * 24 * 24];
__device__ float g_att [BMAX * 4 * 26 * 26];
__device__ float g_pool[BMAX * 2 * 4 * 26 * 26];

__device__ double g_sum[60], g_sq[60];

__device__ float g_wl[4 * 3 * 3 * 10];
__device__ __align__(16) float g_wc[5 * 4 * 10 * 4 * 3 * 3 * 10];
__device__ float g_wc7[4 * 10 * 4 * 4 * 4 * 10];
__device__ float g_wa1[49];
__device__ float g_wa[6 * 4 * 2 * 4 * 7 * 7];

typedef unsigned long long u64;

__device__ __forceinline__ u64 pk2(float lo, float hi) {
    u64 r; asm("mov.b64 %0,{%1,%2};" : "=l"(r) : "f"(lo), "f"(hi)); return r;
}
__device__ __forceinline__ void upk2(u64 v, float& lo, float& hi) {
    asm("mov.b64 {%0,%1},%2;" : "=f"(lo), "=f"(hi) : "l"(v));
}
__device__ __forceinline__ u64 ffma2(u64 a, u64 b, u64 c) {
    u64 d; asm("fma.rn.f32x2 %0,%1,%2,%3;" : "=l"(d) : "l"(a), "l"(b), "l"(c)); return d;
}

__device__ __forceinline__ void rotmap(int r, int u, int v, int K, int& su, int& sv) {
    switch (r & 3) {
        case 0: su = u;         sv = v;         break;
        case 1: su = v;         sv = K - 1 - u; break;
        case 2: su = K - 1 - u; sv = K - 1 - v; break;
        default: su = K - 1 - v; sv = u;        break;
    }
}

__device__ __forceinline__ float warpsum(float v) {
    for (int o = 16; o > 0; o >>= 1) v += __shfl_down_sync(0xffffffffu, v, o);
    return v;
}

__device__ __forceinline__ void bn_smem(int tid, int bnIdx, const float* bng,
                                        const float* bnb, float invN,
                                        float* sc, float* sh) {
    if (tid < 10) {
        if (bnIdx >= 0) {
            double m = g_sum[bnIdx * 10 + tid] * (double)invN;
            double var = g_sq[bnIdx * 10 + tid] * (double)invN - m * m;
            float rstd = rsqrtf((float)var + 2e-5f);
            float s = bng[tid] * rstd;
            sc[tid] = s; sh[tid] = bnb[tid] - (float)m * s;
        } else { sc[tid] = 1.f; sh[tid] = 0.f; }
    }
}

// ---------------- prep ----------------
__global__ void prepk(const float* c1, const float* c2, const float* c3, const float* c4,
                      const float* c5, const float* c6, const float* c7,
                      const float* a1, const float* a2, const float* a3, const float* a4,
                      const float* a5, const float* a6, const float* a7) {
    int tid = blockIdx.x * blockDim.x + threadIdx.x;
    int nth = gridDim.x * blockDim.x;
    const float* cws[5] = {c2, c3, c4, c5, c6};
    const float* aws[6] = {a2, a3, a4, a5, a6, a7};

    for (int idx = tid; idx < 360; idx += nth) {
        int o = idx % 10, t = idx / 10;
        int v = t % 3; t /= 3; int u = t % 3; int r = t / 3;
        int su, sv; rotmap(r, u, v, 3, su, sv);
        g_wl[idx] = c1[o * 9 + su * 3 + sv];
    }
    for (int idx = tid; idx < 5 * 14400; idx += nth) {
        int o = idx % 10; int t = idx / 10;
        int v = t % 3; t /= 3; int u = t % 3; t /= 3;
        int s = t & 3; t >>= 2; int i = t % 10; t /= 10;
        int r = t & 3; int l = t >> 2;
        int sp = (s - r) & 3; int su, sv; rotmap(r, u, v, 3, su, sv);
        g_wc[idx] = cws[l][((o * 10 + i) * 4 + sp) * 9 + su * 3 + sv];
    }
    for (int idx = tid; idx < 25600; idx += nth) {
        int o = idx % 10; int t = idx / 10;
        int v = t & 3; t >>= 2; int u = t & 3; t >>= 2;
        int s = t & 3; t >>= 2; int i = t % 10; int r = t / 10;
        int sp = (s - r) & 3; int su, sv; rotmap(r, u, v, 4, su, sv);
        g_wc7[idx] = c7[((o * 10 + i) * 4 + sp) * 16 + su * 4 + sv];
    }
    for (int idx = tid; idx < 49; idx += nth) g_wa1[idx] = a1[idx] + a1[49 + idx];
    for (int idx = tid; idx < 6 * 1568; idx += nth) {
        int v = idx % 7; int t = idx / 7;
        int u = t % 7; t /= 7; int s = t & 3; t >>= 2;
        int i = t & 1; t >>= 1; int r = t & 3; int l = t >> 2;
        int sp = (s - r) & 3; int su, sv; rotmap(r, u, v, 7, su, sv);
        g_wa[idx] = aws[l][(i * 4 + sp) * 49 + su * 7 + sv];
    }
    for (int idx = tid; idx < 60; idx += nth) { g_sum[idx] = 0.0; g_sq[idx] = 0.0; }
}

// ---------------- layer 1: attention + gate + lifting conv + stats0 ----------------
__global__ void __launch_bounds__(256) l1k(const float* __restrict__ x) {
    __shared__ float xt[34 * 34];
    __shared__ float sxg[784];
    __shared__ float w[49];
    __shared__ float sw[360];
    __shared__ float bsum[10], bsq[10];
    int b = blockIdx.x, tid = threadIdx.x;
    for (int i = tid; i < 34 * 34; i += 256) xt[i] = 0.f;
    for (int i = tid; i < 49; i += 256) w[i] = g_wa1[i];
    for (int i = tid; i < 360; i += 256) sw[i] = g_wl[i];
    if (tid < 10) { bsum[tid] = 0.f; bsq[tid] = 0.f; }
    __syncthreads();
    for (int i = tid; i < 784; i += 256) {
        int y = i / 28, xx = i % 28;
        xt[(y + 3) * 34 + xx + 3] = x[(size_t)b * 784 + i];
    }
    __syncthreads();
    for (int p = tid; p < 784; p += 256) {
        int y = p / 28, xx = p % 28;
        float acc = 0.f;
#pragma unroll
        for (int u = 0; u < 7; u++)
#pragma unroll
            for (int v = 0; v < 7; v++)
                acc = fmaf(xt[(y + u) * 34 + xx + v], w[u * 7 + v], acc);
        float xv = xt[(y + 3) * 34 + xx + 3];
        sxg[p] = xv * (1.f / (1.f + expf(-acc)));
    }
    __syncthreads();
    float ts[10], tq[10];
#pragma unroll
    for (int o = 0; o < 10; o++) { ts[o] = 0.f; tq[o] = 0.f; }
    for (int r = 0; r < 4; r++) {
        for (int pp = tid; pp < 338; pp += 256) {
            int y = pp / 13, x0 = (pp % 13) * 2;
            float a0[10], a1[10];
#pragma unroll
            for (int o = 0; o < 10; o++) { a0[o] = 0.f; a1[o] = 0.f; }
#pragma unroll
            for (int u = 0; u < 3; u++)
#pragma unroll
                for (int v = 0; v < 3; v++) {
                    float xv0 = sxg[(y + u) * 28 + x0 + v];
                    float xv1 = sxg[(y + u) * 28 + x0 + v + 1];
                    const float* wp = &sw[((r * 3 + u) * 3 + v) * 10];
#pragma unroll
                    for (int o = 0; o < 10; o++) {
                        a0[o] = fmaf(xv0, wp[o], a0[o]);
                        a1[o] = fmaf(xv1, wp[o], a1[o]);
                    }
                }
#pragma unroll
            for (int o = 0; o < 10; o++) {
                size_t off = ((((size_t)b * 10 + o) * 4 + r) * 26 + y) * 26 + x0;
                g_buf0[off] = a0[o]; g_buf0[off + 1] = a1[o];
                ts[o] += a0[o] + a1[o];
                tq[o] += a0[o] * a0[o] + a1[o] * a1[o];
            }
        }
    }
#pragma unroll
    for (int o = 0; o < 10; o++) {
        float s = warpsum(ts[o]);
        float q = warpsum(tq[o]);
        if ((tid & 31) == 0) { atomicAdd(&bsum[o], s); atomicAdd(&bsq[o], q); }
    }
    __syncthreads();
    if (tid < 10) {
        atomicAdd(&g_sum[tid], (double)bsum[tid]);
        atomicAdd(&g_sq[tid], (double)bsq[tid]);
    }
}

// ---------------- layer-2 pooled (mean,max) with BN0 inline ----------------
__global__ void __launch_bounds__(256) pool26(const float* __restrict__ in, int B,
                                              const float* __restrict__ bng,
                                              const float* __restrict__ bnb, float invN) {
    const int H2 = 676;
    __shared__ float sc[10], sh[10];
    bn_smem(threadIdx.x, 0, bng, bnb, invN, sc, sh);
    __syncthreads();
    int total = B * 4 * H2;
    for (int idx = blockIdx.x * blockDim.x + threadIdx.x; idx < total;
         idx += gridDim.x * blockDim.x) {
        int pos = idx % H2;
        int s = (idx / H2) & 3;
        int b = idx / (4 * H2);
        const float* p = in + ((size_t)b * 40 + s) * H2 + pos;
        float sum = 0.f, mx = -3.4e38f;
#pragma unroll
        for (int c = 0; c < 10; c++) {
            float v = fmaf(p[(size_t)c * 4 * H2], sc[c], sh[c]);
            v = v > 0.f ? v : 0.f;
            sum += v; mx = fmaxf(mx, v);
        }
        g_pool[((size_t)b * 8 + s) * H2 + pos]     = sum * 0.1f;
        g_pool[((size_t)b * 8 + 4 + s) * H2 + pos] = mx;
    }
}

// ---------------- layer-2 GG attention conv, f32x2 pixel pairs, bank-safe stride
__global__ void __launch_bounds__(192) attk2() {
    constexpr int H = 26, H2 = 676, PWT = 36;   // 36: even (u64-aligned), not mult of 16
    __shared__ __align__(16) float pt[8 * PWT * PWT + 16];
    __shared__ __align__(8) float wd[784];
    int b = blockIdx.x >> 2, r = blockIdx.x & 3, tid = threadIdx.x;
    for (int i = tid; i < 8 * PWT * PWT + 16; i += 192) pt[i] = 0.f;
    for (int i = tid; i < 392; i += 192) {
        float w = g_wa[r * 392 + i];
        wd[2 * i] = w; wd[2 * i + 1] = w;
    }
    __syncthreads();
    const float* pb = g_pool + (size_t)b * 8 * H2;
    for (int idx = tid; idx < 8 * H2; idx += 192) {
        int js = idx / H2, pos = idx - js * H2;
        int y = pos / H, x = pos - y * H;
        pt[(js * PWT + y + 3) * PWT + x + 3] = pb[idx];
    }
    __syncthreads();
    constexpr int NQA = 7;
    for (int t = tid; t < H * NQA; t += 192) {
        int q = t % NQA, y = t / NQA, x0 = q * 4;
        u64 acc01 = 0ull, acc23 = 0ull;
#pragma unroll
        for (int js = 0; js < 8; js++) {
#pragma unroll
            for (int u = 0; u < 7; u++) {
                const u64* rp = (const u64*)&pt[(js * PWT + y + u) * PWT + x0];
                u64 P0 = rp[0], P1 = rp[1], P2 = rp[2], P3 = rp[3], P4 = rp[4];
                float p0l, p0h, p1l, p1h, p2l, p2h, p3l, p3h, p4l, p4h;
                upk2(P0, p0l, p0h); upk2(P1, p1l, p1h); upk2(P2, p2l, p2h);
                upk2(P3, p3l, p3h); upk2(P4, p4l, p4h);
                u64 O0 = pk2(p0h, p1l), O1 = pk2(p1h, p2l), O2 = pk2(p2h, p3l), O3 = pk2(p3h, p4l);
                const u64* wp = (const u64*)&wd[(js * 49 + u * 7) * 2];
                acc01 = ffma2(P0, wp[0], acc01); acc23 = ffma2(P1, wp[0], acc23);
                acc01 = ffma2(O0, wp[1], acc01); acc23 = ffma2(O1, wp[1], acc23);
                acc01 = ffma2(P1, wp[2], acc01); acc23 = ffma2(P2, wp[2], acc23);
                acc01 = ffma2(O1, wp[3], acc01); acc23 = ffma2(O2, wp[3], acc23);
                acc01 = ffma2(P2, wp[4], acc01); acc23 = ffma2(P3, wp[4], acc23);
                acc01 = ffma2(O2, wp[5], acc01); acc23 = ffma2(O3, wp[5], acc23);
                acc01 = ffma2(P3, wp[6], acc01); acc23 = ffma2(P4, wp[6], acc23);
            }
        }
        float a0, a1, a2, a3; upk2(acc01, a0, a1); upk2(acc23, a2, a3);
        float* ob = &g_att[((size_t)b * 4 + r) * H2 + y * H];
        if (x0 < H)     ob[x0]     = 1.f / (1.f + expf(-a0));
        if (x0 + 1 < H) ob[x0 + 1] = 1.f / (1.f + expf(-a1));
        if (x0 + 2 < H) ob[x0 + 2] = 1.f / (1.f + expf(-a2));
        if (x0 + 3 < H) ob[x0 + 3] = 1.f / (1.f + expf(-a3));
    }
}

// ---------------- layer-2 GG conv, y-split x3, BN0 inline, stats1 ----------------
__global__ void __launch_bounds__(192, 2) convL2(const float* __restrict__ in,
                                                 float* __restrict__ out,
                                                 const float* __restrict__ bng,
                                                 const float* __restrict__ bnb, float invN) {
    extern __shared__ float sm[];
    float* sx = sm;            // 40*10*28 = 11200 (+8 pad)
    float* sw = sm + 11208;    // 14400
    __shared__ float bsum[10], bsq[10], sc[10], sh[10];
    int b = blockIdx.x / 3, yt = blockIdx.x % 3, y0 = yt * 8;
    int tid = threadIdx.x;
    if (tid < 10) { bsum[tid] = 0.f; bsq[tid] = 0.f; }
    bn_smem(tid, 0, bng, bnb, invN, sc, sh);
    if (tid < 8) sx[11200 + tid] = 0.f;
    __syncthreads();
    const float* inb = in + (size_t)b * 27040;
    const float* attp = g_att + (size_t)b * 2704;
    for (int idx = tid; idx < 40 * 10 * 26; idx += 192) {
        int x = idx % 26; int t = idx / 26; int yy = t % 10; int is = t / 10;
        int gy = y0 + yy;
        float v = inb[is * 676 + gy * 26 + x];
        v = fmaf(v, sc[is >> 2], sh[is >> 2]);
        v = v > 0.f ? v : 0.f;
        v *= __ldg(&attp[(is & 3) * 676 + gy * 26 + x]);
        sx[(is * 10 + yy) * 28 + x] = v;
    }
    {
        const float4* wg = (const float4*)g_wc;
        float4* swv = (float4*)sw;
        for (int i = tid; i < 3600; i += 192) swv[i] = wg[i];
    }
    __syncthreads();

    float ts[10], tq[10];
#pragma unroll
    for (int o = 0; o < 10; o++) { ts[o] = 0.f; tq[o] = 0.f; }

    {
        int task = tid;
        int q = task % 6;
        int yy = (task / 6) % 8;
        int r = task / 48;
        int x0 = q * 4;
        u64 acc[4][5];
#pragma unroll
        for (int p = 0; p < 4; p++)
#pragma unroll
            for (int k = 0; k < 5; k++) acc[p][k] = 0ull;
        const float* wr = &sw[r * 3600];
        const float* xb0 = &sx[yy * 28 + x0];
        for (int is = 0; is < 40; is++) {
            const float* xb = xb0 + is * 280;
            const float* wb = wr + is * 90;
#pragma unroll
            for (int u = 0; u < 3; u++) {
                float4 v4 = *(const float4*)(xb + u * 28);
                float2 v2 = *(const float2*)(xb + u * 28 + 4);
                u64 xd[6];
                xd[0] = pk2(v4.x, v4.x); xd[1] = pk2(v4.y, v4.y);
                xd[2] = pk2(v4.z, v4.z); xd[3] = pk2(v4.w, v4.w);
                xd[4] = pk2(v2.x, v2.x); xd[5] = pk2(v2.y, v2.y);
#pragma unroll
                for (int v = 0; v < 3; v++) {
                    const u64* wp = (const u64*)(wb + u * 30 + v * 10);
#pragma unroll
                    for (int k = 0; k < 5; k++) {
                        u64 w2 = wp[k];
#pragma unroll
                        for (int p = 0; p < 4; p++)
                            acc[p][k] = ffma2(xd[v + p], w2, acc[p][k]);
                    }
                }
            }
        }
        int y = y0 + yy;
#pragma unroll
        for (int p = 0; p < 4; p++) {
            int x = x0 + p;
#pragma unroll
            for (int k = 0; k < 5; k++) {
                float lo, hi; upk2(acc[p][k], lo, hi);
                ts[2 * k] += lo;     tq[2 * k] += lo * lo;
                ts[2 * k + 1] += hi; tq[2 * k + 1] += hi * hi;
                size_t o0 = ((((size_t)b * 10 + 2 * k) * 4 + r) * 24 + y) * 24 + x;
                out[o0] = lo;
                out[o0 + (size_t)2304] = hi;
            }
        }
    }
#pragma unroll
    for (int o = 0; o < 10; o++) {
        float s = warpsum(ts[o]);
        float qv = warpsum(tq[o]);
        if ((tid & 31) == 0) { atomicAdd(&bsum[o], s); atomicAdd(&bsq[o], qv); }
    }
    __syncthreads();
    if (tid < 10) {
        atomicAdd(&g_sum[10 + tid], (double)bsum[tid]);
        atomicAdd(&g_sq[10 + tid], (double)bsq[tid]);
    }
}

// ---------------- fused layer ----------------
template <int H, int NT, int PXCH, int GIMG, bool LPOOL>
__global__ void __launch_bounds__(NT, 2) fusedgg(const float* __restrict__ in,
                                                 float* __restrict__ out,
                                                 int wlayer, int alayer, int statsIdx,
                                                 int bnIdx, const float* __restrict__ bng,
                                                 const float* __restrict__ bnb, float invN) {
    constexpr int HO = H - 2, WO = H - 2, HP = (H + 3) & ~3;
    constexpr int H2 = H * H, PLANE = H * HP;
    constexpr int NQ = (WO + PXCH - 1) / PXCH;
    constexpr int TASKS = GIMG * 4 * HO * NQ;
    constexpr int PW4R = ((H + 6) + 3) & ~3;
    constexpr int PW4 = (PW4R % 16 == 0) ? PW4R + 4 : PW4R;   // avoid bank-aliased stride
    constexpr int TILE = 8 * PW4 * PW4;
    constexpr int NQA = (H + 3) / 4;
    extern __shared__ float sm[];
    float* sx = sm;
    float* sw = sm + GIMG * 40 * PLANE + 8;
    float* tile = sw;
    float* wa_s = sw + TILE + 16;
    float* att_s = wa_s + 1568;
    __shared__ float bsum[10], bsq[10], sc[10], sh[10];
    int grp = blockIdx.x, tid = threadIdx.x;
    if (tid < 10) { bsum[tid] = 0.f; bsq[tid] = 0.f; }
    bn_smem(tid, bnIdx, bng, bnb, invN, sc, sh);
    if (tid < 8) sx[GIMG * 40 * PLANE + tid] = 0.f;
    __syncthreads();

    for (int li = 0; li < GIMG; li++) {
        int b = grp * GIMG + li;
        if (LPOOL) {
            const float* inb = in + (size_t)b * 40 * 576;
            for (int idx = tid; idx < 40 * H2; idx += NT) {
                int is = idx / H2, pos = idx - is * H2;
                int y = pos / H, x = pos - y * H;
                const float* p = inb + (size_t)is * 576 + (2 * y) * 24 + 2 * x;
                float2 A = *(const float2*)p;
                float2 Bv = *(const float2*)(p + 24);
                float s = sc[is >> 2], t = sh[is >> 2];
                float v0 = fmaf(A.x, s, t), v1 = fmaf(A.y, s, t);
                float v2 = fmaf(Bv.x, s, t), v3 = fmaf(Bv.y, s, t);
                float v = fmaxf(fmaxf(v0, v1), fmaxf(v2, v3));
                v = v > 0.f ? v : 0.f;
                sx[((li * 40 + is) * H + y) * HP + x] = v;
            }
        } else {
            const float* inb = in + (size_t)b * 40 * H2;
            for (int idx = tid; idx < 40 * H2; idx += NT) {
                int is = idx / H2, pos = idx - is * H2;
                int y = pos / H, x = pos - y * H;
                float v = inb[idx];
                v = fmaf(v, sc[is >> 2], sh[is >> 2]);
                v = v > 0.f ? v : 0.f;
                sx[((li * 40 + is) * H + y) * HP + x] = v;
            }
        }
    }
    for (int i = tid; i < 1568; i += NT) wa_s[i] = g_wa[alayer * 1568 + i];
    __syncthreads();

    for (int li = 0; li < GIMG; li++) {
        for (int i = tid; i < TILE; i += NT) tile[i] = 0.f;
        __syncthreads();
        for (int idx = tid; idx < 4 * H2; idx += NT) {
            int s = idx / H2, pos = idx - s * H2;
            int y = pos / H, x = pos - y * H;
            float sum = 0.f, mx = -3.4e38f;
#pragma unroll
            for (int c = 0; c < 10; c++) {
                float v = sx[((li * 40 + c * 4 + s) * H + y) * HP + x];
                sum += v; mx = fmaxf(mx, v);
            }
            tile[(s * PW4 + y + 3) * PW4 + x + 3] = sum * 0.1f;
            tile[((4 + s) * PW4 + y + 3) * PW4 + x + 3] = mx;
        }
        __syncthreads();
        for (int t = tid; t < 4 * NQA * H; t += NT) {
            int q = t % NQA; int y = (t / NQA) % H; int r = t / (NQA * H);
            int x0 = q * 4;
            float a0 = 0.f, a1 = 0.f, a2 = 0.f, a3 = 0.f;
            const float* wb0 = &wa_s[r * 392];
#pragma unroll
            for (int js = 0; js < 8; js++) {
#pragma unroll
                for (int u = 0; u < 7; u++) {
                    const float* rowp = &tile[(js * PW4 + y + u) * PW4 + x0];
                    float4 A = *(const float4*)rowp;
                    float4 Bv = *(const float4*)(rowp + 4);
                    float2 Cv = *(const float2*)(rowp + 8);
                    float rr[10] = {A.x, A.y, A.z, A.w, Bv.x, Bv.y, Bv.z, Bv.w, Cv.x, Cv.y};
                    const float* wb = &wb0[js * 49 + u * 7];
#pragma unroll
                    for (int v = 0; v < 7; v++) {
                        float w = wb[v];
                        a0 = fmaf(rr[v], w, a0);
                        a1 = fmaf(rr[v + 1], w, a1);
                        a2 = fmaf(rr[v + 2], w, a2);
                        a3 = fmaf(rr[v + 3], w, a3);
                    }
                }
            }
            float* ob = &att_s[(li * 4 + r) * H2 + y * H];
            if (x0 < H)     ob[x0]     = 1.f / (1.f + expf(-a0));
            if (x0 + 1 < H) ob[x0 + 1] = 1.f / (1.f + expf(-a1));
            if (x0 + 2 < H) ob[x0 + 2] = 1.f / (1.f + expf(-a2));
            if (x0 + 3 < H) ob[x0 + 3] = 1.f / (1.f + expf(-a3));
        }
        __syncthreads();
    }

    for (int li = 0; li < GIMG; li++)
        for (int idx = tid; idx < 40 * H2; idx += NT) {
            int is = idx / H2, pos = idx - is * H2;
            int y = pos / H, x = pos - y * H;
            sx[((li * 40 + is) * H + y) * HP + x] *= att_s[(li * 4 + (is & 3)) * H2 + pos];
        }
    __syncthreads();
    {
        const float4* wg = (const float4*)&g_wc[wlayer * 14400];
        float4* swv = (float4*)sw;
        for (int i = tid; i < 3600; i += NT) swv[i] = wg[i];
    }
    __syncthreads();

    float ts[10], tq[10];
#pragma unroll
    for (int o = 0; o < 10; o++) { ts[o] = 0.f; tq[o] = 0.f; }

    for (int task = tid; task < TASKS; task += NT) {
        int q = task % NQ;
        int t2 = task / NQ;
        int y = t2 % HO; t2 /= HO;
        int r = t2 & 3; int li = t2 >> 2;
        int x0 = q * PXCH;
        u64 acc[PXCH][5];
#pragma unroll
        for (int p = 0; p < PXCH; p++)
#pragma unroll
            for (int k = 0; k < 5; k++) acc[p][k] = 0ull;
        const float* wr = &sw[r * 3600];
        const float* xb0 = &sx[(li * 40 * H + y) * HP + x0];
        for (int is = 0; is < 40; is++) {
            const float* xb = xb0 + is * PLANE;
            const float* wb = wr + is * 90;
#pragma unroll
            for (int u = 0; u < 3; u++) {
                u64 xd[PXCH + 2];
                if (PXCH == 4) {
                    float4 v4 = *(const float4*)(xb + u * HP);
                    float2 v2 = *(const float2*)(xb + u * HP + 4);
                    xd[0] = pk2(v4.x, v4.x); xd[1] = pk2(v4.y, v4.y);
                    xd[2] = pk2(v4.z, v4.z); xd[3] = pk2(v4.w, v4.w);
                    xd[4] = pk2(v2.x, v2.x); xd[5] = pk2(v2.y, v2.y);
                } else {
                    float2 vA = *(const float2*)(xb + u * HP);
                    float2 vB = *(const float2*)(xb + u * HP + 2);
                    xd[0] = pk2(vA.x, vA.x); xd[1] = pk2(vA.y, vA.y);
                    xd[2] = pk2(vB.x, vB.x); xd[3] = pk2(vB.y, vB.y);
                }
#pragma unroll
                for (int v = 0; v < 3; v++) {
                    const u64* wp = (const u64*)(wb + u * 30 + v * 10);
#pragma unroll
                    for (int k = 0; k < 5; k++) {
                        u64 w2 = wp[k];
#pragma unroll
                        for (int p = 0; p < PXCH; p++)
                            acc[p][k] = ffma2(xd[v + p], w2, acc[p][k]);
                    }
                }
            }
        }
        int b = grp * GIMG + li;
#pragma unroll
        for (int p = 0; p < PXCH; p++) {
            int x = x0 + p;
            if (x < WO) {
#pragma unroll
                for (int k = 0; k < 5; k++) {
                    float lo, hi; upk2(acc[p][k], lo, hi);
                    ts[2 * k] += lo;     tq[2 * k] += lo * lo;
                    ts[2 * k + 1] += hi; tq[2 * k + 1] += hi * hi;
                    size_t o0 = ((((size_t)b * 10 + 2 * k) * 4 + r) * HO + y) * WO + x;
                    out[o0] = lo;
                    out[o0 + (size_t)4 * HO * WO] = hi;
                }
            }
        }
    }
#pragma unroll
    for (int o = 0; o < 10; o++) {
        float s = warpsum(ts[o]);
        float qv = warpsum(tq[o]);
        if ((tid & 31) == 0) { atomicAdd(&bsum[o], s); atomicAdd(&bsq[o], qv); }
    }
    __syncthreads();
    if (tid < 10) {
        atomicAdd(&g_sum[statsIdx * 10 + tid], (double)bsum[tid]);
        atomicAdd(&g_sq[statsIdx * 10 + tid], (double)bsq[tid]);
    }
}

// ---------------- layer 7 fused ----------------
__global__ void __launch_bounds__(64) conv7k(const float* __restrict__ in,
                                             float* __restrict__ outp,
                                             const float* __restrict__ bng,
                                             const float* __restrict__ bnb, float invN) {
    __shared__ float sx[640], yv[40], sc[10], sh[10];
    __shared__ float tile[8 * 12 * 12 + 16];
    __shared__ float wa_s[1568];
    __shared__ float att_s[64];
    int b = blockIdx.x, tid = threadIdx.x;
    bn_smem(tid, 5, bng, bnb, invN, sc, sh);
    for (int i = tid; i < 8 * 144 + 16; i += 64) tile[i] = 0.f;
    for (int i = tid; i < 1568; i += 64) wa_s[i] = g_wa[5 * 1568 + i];
    __syncthreads();
    for (int idx = tid; idx < 640; idx += 64) {
        int c = idx >> 6;
        float v = in[(size_t)b * 640 + idx];
        v = fmaf(v, sc[c], sh[c]);
        sx[idx] = v > 0.f ? v : 0.f;
    }
    __syncthreads();
    if (tid < 64) {
        int s = tid / 16, pos = tid & 15;
        int y = pos >> 2, x = pos & 3;
        float sum = 0.f, mx = -3.4e38f;
#pragma unroll
        for (int c = 0; c < 10; c++) {
            float v = sx[(c * 4 + s) * 16 + pos];
            sum += v; mx = fmaxf(mx, v);
        }
        tile[(s * 12 + y + 3) * 12 + x + 3] = sum * 0.1f;
        tile[((4 + s) * 12 + y + 3) * 12 + x + 3] = mx;
    }
    __syncthreads();
    if (tid < 64) {
        int r = tid / 16, pos = tid & 15;
        int y = pos >> 2, x = pos & 3;
        float acc = 0.f;
        const float* wb0 = &wa_s[r * 392];
#pragma unroll
        for (int js = 0; js < 8; js++)
#pragma unroll
            for (int u = 0; u < 7; u++) {
                const float* rowp = &tile[(js * 12 + y + u) * 12 + x];
                const float* wb = &wb0[js * 49 + u * 7];
#pragma unroll
                for (int v = 0; v < 7; v++) acc = fmaf(rowp[v], wb[v], acc);
            }
        att_s[r * 16 + pos] = 1.f / (1.f + expf(-acc));
    }
    __syncthreads();
    for (int idx = tid; idx < 640; idx += 64) {
        int is = (idx >> 4) & 3;
        sx[idx] *= att_s[is * 16 + (idx & 15)];
    }
    __syncthreads();
    if (tid < 40) {
        int r = tid / 10, o = tid % 10;
        float acc = 0.f;
        for (int is = 0; is < 40; is++) {
#pragma unroll
            for (int t = 0; t < 16; t++)
                acc = fmaf(sx[is * 16 + t], __ldg(&g_wc7[((r * 40 + is) * 16 + t) * 10 + o]), acc);
        }
        yv[r * 10 + o] = acc;
    }
    __syncthreads();
    if (tid < 10) {
        float m = yv[tid];
        for (int r = 1; r < 4; r++) m = fmaxf(m, yv[r * 10 + tid]);
        outp[(size_t)b * 10 + tid] = m;
    }
}

// ---------------- launch ----------------
extern "C" void kernel_launch(void* const* d_in, const int* in_sizes, int n_in,
                              void* d_out, int out_size) {
    const float* x  = (const float*)d_in[0];
    const float* c1 = (const float*)d_in[1];
    const float* a1 = (const float*)d_in[2];
    const float* c2 = (const float*)d_in[3];
    const float* a2 = (const float*)d_in[4];
    const float* c3 = (const float*)d_in[5];
    const float* a3 = (const float*)d_in[6];
    const float* c4 = (const float*)d_in[7];
    const float* a4 = (const float*)d_in[8];
    const float* c5 = (const float*)d_in[9];
    const float* a5 = (const float*)d_in[10];
    const float* c6 = (const float*)d_in[11];
    const float* a6 = (const float*)d_in[12];
    const float* c7 = (const float*)d_in[13];
    const float* a7 = (const float*)d_in[14];
    const float* bn_g[6] = {(const float*)d_in[15], (const float*)d_in[17], (const float*)d_in[19],
                            (const float*)d_in[21], (const float*)d_in[23], (const float*)d_in[25]};
    const float* bn_b[6] = {(const float*)d_in[16], (const float*)d_in[18], (const float*)d_in[20],
                            (const float*)d_in[22], (const float*)d_in[24], (const float*)d_in[26]};
    float* out = (float*)d_out;

    int B = in_sizes[0] / 784;
    if (B > BMAX) B = BMAX;

    float *b0, *b1;
    cudaGetSymbolAddress((void**)&b0, g_buf0);
    cudaGetSymbolAddress((void**)&b1, g_buf1);

    const int SML2 = (11208 + 14400) * 4;
    const int SM3 = (2 * 40 * 12 * 12 + 8 + 14400) * 4;
    const int SM4 = (2 * 40 * 10 * 12 + 8 + 14400) * 4;
    const int SM5 = (4 * 40 * 8 * 8 + 8 + 14400) * 4;
    const int SM6 = (4 * 40 * 6 * 8 + 8 + 14400) * 4;
    cudaFuncSetAttribute((const void*)convL2, cudaFuncAttributeMaxDynamicSharedMemorySize, SML2);
    cudaFuncSetAttribute((const void*)fusedgg<12, 256, 4, 2, true>,  cudaFuncAttributeMaxDynamicSharedMemorySize, SM3);
    cudaFuncSetAttribute((const void*)fusedgg<10, 256, 4, 2, false>, cudaFuncAttributeMaxDynamicSharedMemorySize, SM4);
    cudaFuncSetAttribute((const void*)fusedgg<8, 288, 2, 4, false>,  cudaFuncAttributeMaxDynamicSharedMemorySize, SM5);
    cudaFuncSetAttribute((const void*)fusedgg<6, 128, 4, 4, false>,  cudaFuncAttributeMaxDynamicSharedMemorySize, SM6);

    prepk<<<64, 128>>>(c1, c2, c3, c4, c5, c6, c7, a1, a2, a3, a4, a5, a6, a7);

    l1k<<<B, 256>>>(x);

    float invN0 = 1.f / (float)(B * 4 * 676);
    {
        int tp = B * 4 * 676;
        pool26<<<(tp + 255) / 256, 256>>>(b0, B, bn_g[0], bn_b[0], invN0);
        attk2<<<B * 4, 192>>>();
        convL2<<<B * 3, 192, SML2>>>(b0, b1, bn_g[0], bn_b[0], invN0);
    }

    fusedgg<12, 256, 4, 2, true><<<B / 2, 256, SM3>>>(b1, b0, 1, 1, 2, 1, bn_g[1], bn_b[1], 1.f / (float)(B * 4 * 576));
    fusedgg<10, 256, 4, 2, false><<<B / 2, 256, SM4>>>(b0, b1, 2, 2, 3, 2, bn_g[2], bn_b[2], 1.f / (float)(B * 4 * 100));
    fusedgg<8, 288, 2, 4, false><<<B / 4, 288, SM5>>>(b1, b0, 3, 3, 4, 3, bn_g[3], bn_b[3], 1.f / (float)(B * 4 * 64));
    fusedgg<6, 128, 4, 4, false><<<B / 4, 128, SM6>>>(b0, b1, 4, 4, 5, 4, bn_g[4], bn_b[4], 1.f / (float)(B * 4 * 36));
    conv7k<<<B, 64>>>(b1, out, bn_g[5], bn_b[5], 1.f / (float)(B * 4 * 16));
}

// round 10
// speedup vs baseline: 1.0202x; 1.0202x over previous
#include <cuda_runtime.h>
#include <cstdint>
#include <math.h>

#define BMAX 2048
__device__ float g_buf0[BMAX * 10 * 4 * 26 * 26];
__device__ float g_buf1[BMAX * 10 * 4 * 24 * 24];
__device__ float g_att [BMAX * 4 * 26 * 26];
__device__ float g_pool[BMAX * 2 * 4 * 26 * 26];

__device__ double g_sum[60], g_sq[60];

__device__ float g_wl[4 * 3 * 3 * 10];
__device__ __align__(16) float g_wc[5 * 4 * 10 * 4 * 3 * 3 * 10];
__device__ float g_wc7[4 * 10 * 4 * 4 * 4 * 10];
__device__ float g_wa1[49];
__device__ float g_wa[6 * 4 * 2 * 4 * 7 * 7];

typedef unsigned long long u64;

__device__ __forceinline__ u64 pk2(float lo, float hi) {
    u64 r; asm("mov.b64 %0,{%1,%2};" : "=l"(r) : "f"(lo), "f"(hi)); return r;
}
__device__ __forceinline__ void upk2(u64 v, float& lo, float& hi) {
    asm("mov.b64 {%0,%1},%2;" : "=f"(lo), "=f"(hi) : "l"(v));
}
__device__ __forceinline__ u64 ffma2(u64 a, u64 b, u64 c) {
    u64 d; asm("fma.rn.f32x2 %0,%1,%2,%3;" : "=l"(d) : "l"(a), "l"(b), "l"(c)); return d;
}

__device__ __forceinline__ void rotmap(int r, int u, int v, int K, int& su, int& sv) {
    switch (r & 3) {
        case 0: su = u;         sv = v;         break;
        case 1: su = v;         sv = K - 1 - u; break;
        case 2: su = K - 1 - u; sv = K - 1 - v; break;
        default: su = K - 1 - v; sv = u;        break;
    }
}

__device__ __forceinline__ float warpsum(float v) {
    for (int o = 16; o > 0; o >>= 1) v += __shfl_down_sync(0xffffffffu, v, o);
    return v;
}

__device__ __forceinline__ void bn_smem(int tid, int bnIdx, const float* bng,
                                        const float* bnb, float invN,
                                        float* sc, float* sh) {
    if (tid < 10) {
        if (bnIdx >= 0) {
            double m = g_sum[bnIdx * 10 + tid] * (double)invN;
            double var = g_sq[bnIdx * 10 + tid] * (double)invN - m * m;
            float rstd = rsqrtf((float)var + 2e-5f);
            float s = bng[tid] * rstd;
            sc[tid] = s; sh[tid] = bnb[tid] - (float)m * s;
        } else { sc[tid] = 1.f; sh[tid] = 0.f; }
    }
}

// ---------------- prep ----------------
__global__ void prepk(const float* c1, const float* c2, const float* c3, const float* c4,
                      const float* c5, const float* c6, const float* c7,
                      const float* a1, const float* a2, const float* a3, const float* a4,
                      const float* a5, const float* a6, const float* a7) {
    int tid = blockIdx.x * blockDim.x + threadIdx.x;
    int nth = gridDim.x * blockDim.x;
    const float* cws[5] = {c2, c3, c4, c5, c6};
    const float* aws[6] = {a2, a3, a4, a5, a6, a7};

    for (int idx = tid; idx < 360; idx += nth) {
        int o = idx % 10, t = idx / 10;
        int v = t % 3; t /= 3; int u = t % 3; int r = t / 3;
        int su, sv; rotmap(r, u, v, 3, su, sv);
        g_wl[idx] = c1[o * 9 + su * 3 + sv];
    }
    for (int idx = tid; idx < 5 * 14400; idx += nth) {
        int o = idx % 10; int t = idx / 10;
        int v = t % 3; t /= 3; int u = t % 3; t /= 3;
        int s = t & 3; t >>= 2; int i = t % 10; t /= 10;
        int r = t & 3; int l = t >> 2;
        int sp = (s - r) & 3; int su, sv; rotmap(r, u, v, 3, su, sv);
        g_wc[idx] = cws[l][((o * 10 + i) * 4 + sp) * 9 + su * 3 + sv];
    }
    for (int idx = tid; idx < 25600; idx += nth) {
        int o = idx % 10; int t = idx / 10;
        int v = t & 3; t >>= 2; int u = t & 3; t >>= 2;
        int s = t & 3; t >>= 2; int i = t % 10; int r = t / 10;
        int sp = (s - r) & 3; int su, sv; rotmap(r, u, v, 4, su, sv);
        g_wc7[idx] = c7[((o * 10 + i) * 4 + sp) * 16 + su * 4 + sv];
    }
    for (int idx = tid; idx < 49; idx += nth) g_wa1[idx] = a1[idx] + a1[49 + idx];
    for (int idx = tid; idx < 6 * 1568; idx += nth) {
        int v = idx % 7; int t = idx / 7;
        int u = t % 7; t /= 7; int s = t & 3; t >>= 2;
        int i = t & 1; t >>= 1; int r = t & 3; int l = t >> 2;
        int sp = (s - r) & 3; int su, sv; rotmap(r, u, v, 7, su, sv);
        g_wa[idx] = aws[l][(i * 4 + sp) * 49 + su * 7 + sv];
    }
    for (int idx = tid; idx < 60; idx += nth) { g_sum[idx] = 0.0; g_sq[idx] = 0.0; }
}

// ---------------- layer 1: attention + gate + lifting conv + stats0 ----------------
__global__ void __launch_bounds__(256) l1k(const float* __restrict__ x) {
    __shared__ float xt[34 * 34];
    __shared__ float sxg[784];
    __shared__ float w[49];
    __shared__ float sw[360];
    __shared__ float bsum[10], bsq[10];
    int b = blockIdx.x, tid = threadIdx.x;
    for (int i = tid; i < 34 * 34; i += 256) xt[i] = 0.f;
    for (int i = tid; i < 49; i += 256) w[i] = g_wa1[i];
    for (int i = tid; i < 360; i += 256) sw[i] = g_wl[i];
    if (tid < 10) { bsum[tid] = 0.f; bsq[tid] = 0.f; }
    __syncthreads();
    for (int i = tid; i < 784; i += 256) {
        int y = i / 28, xx = i % 28;
        xt[(y + 3) * 34 + xx + 3] = x[(size_t)b * 784 + i];
    }
    __syncthreads();
    for (int p = tid; p < 784; p += 256) {
        int y = p / 28, xx = p % 28;
        float acc = 0.f;
#pragma unroll
        for (int u = 0; u < 7; u++)
#pragma unroll
            for (int v = 0; v < 7; v++)
                acc = fmaf(xt[(y + u) * 34 + xx + v], w[u * 7 + v], acc);
        float xv = xt[(y + 3) * 34 + xx + 3];
        sxg[p] = xv * (1.f / (1.f + expf(-acc)));
    }
    __syncthreads();
    float ts[10], tq[10];
#pragma unroll
    for (int o = 0; o < 10; o++) { ts[o] = 0.f; tq[o] = 0.f; }
    for (int r = 0; r < 4; r++) {
        for (int pp = tid; pp < 338; pp += 256) {
            int y = pp / 13, x0 = (pp % 13) * 2;
            float a0[10], a1[10];
#pragma unroll
            for (int o = 0; o < 10; o++) { a0[o] = 0.f; a1[o] = 0.f; }
#pragma unroll
            for (int u = 0; u < 3; u++)
#pragma unroll
                for (int v = 0; v < 3; v++) {
                    float xv0 = sxg[(y + u) * 28 + x0 + v];
                    float xv1 = sxg[(y + u) * 28 + x0 + v + 1];
                    const float* wp = &sw[((r * 3 + u) * 3 + v) * 10];
#pragma unroll
                    for (int o = 0; o < 10; o++) {
                        a0[o] = fmaf(xv0, wp[o], a0[o]);
                        a1[o] = fmaf(xv1, wp[o], a1[o]);
                    }
                }
#pragma unroll
            for (int o = 0; o < 10; o++) {
                size_t off = ((((size_t)b * 10 + o) * 4 + r) * 26 + y) * 26 + x0;
                g_buf0[off] = a0[o]; g_buf0[off + 1] = a1[o];
                ts[o] += a0[o] + a1[o];
                tq[o] += a0[o] * a0[o] + a1[o] * a1[o];
            }
        }
    }
#pragma unroll
    for (int o = 0; o < 10; o++) {
        float s = warpsum(ts[o]);
        float q = warpsum(tq[o]);
        if ((tid & 31) == 0) { atomicAdd(&bsum[o], s); atomicAdd(&bsq[o], q); }
    }
    __syncthreads();
    if (tid < 10) {
        atomicAdd(&g_sum[tid], (double)bsum[tid]);
        atomicAdd(&g_sq[tid], (double)bsq[tid]);
    }
}

// ---------------- layer-2 pooled (mean,max) with BN0 inline ----------------
__global__ void __launch_bounds__(256) pool26(const float* __restrict__ in, int B,
                                              const float* __restrict__ bng,
                                              const float* __restrict__ bnb, float invN) {
    const int H2 = 676;
    __shared__ float sc[10], sh[10];
    bn_smem(threadIdx.x, 0, bng, bnb, invN, sc, sh);
    __syncthreads();
    int total = B * 4 * H2;
    for (int idx = blockIdx.x * blockDim.x + threadIdx.x; idx < total;
         idx += gridDim.x * blockDim.x) {
        int pos = idx % H2;
        int s = (idx / H2) & 3;
        int b = idx / (4 * H2);
        const float* p = in + ((size_t)b * 40 + s) * H2 + pos;
        float sum = 0.f, mx = -3.4e38f;
#pragma unroll
        for (int c = 0; c < 10; c++) {
            float v = fmaf(p[(size_t)c * 4 * H2], sc[c], sh[c]);
            v = v > 0.f ? v : 0.f;
            sum += v; mx = fmaxf(mx, v);
        }
        g_pool[((size_t)b * 8 + s) * H2 + pos]     = sum * 0.1f;
        g_pool[((size_t)b * 8 + 4 + s) * H2 + pos] = mx;
    }
}

// ---------------- layer-2 GG attention conv: one block per image, all 4 rotations,
// tile built once, conflict-free lane map (y-major), PWT=34
__global__ void __launch_bounds__(256) attk2() {
    constexpr int H = 26, H2 = 676, PWT = 34;
    extern __shared__ __align__(16) float dsm[];
    float* pt = dsm;               // 8*34*34 = 9248
    float* wd = dsm + 9248;        // 4*392*2 = 3136
    int b = blockIdx.x, tid = threadIdx.x;
    for (int i = tid; i < 9248; i += 256) pt[i] = 0.f;
    for (int i = tid; i < 1568; i += 256) {
        float w = g_wa[i];        // layer-0 attention weights, all rotations
        wd[2 * i] = w; wd[2 * i + 1] = w;
    }
    __syncthreads();
    const float* pb = g_pool + (size_t)b * 8 * H2;
    for (int idx = tid; idx < 8 * H2; idx += 256) {
        int js = idx / H2, pos = idx - js * H2;
        int y = pos / H, x = pos - y * H;
        pt[(js * PWT + y + 3) * PWT + x + 3] = pb[idx];
    }
    __syncthreads();
    for (int t = tid; t < 728; t += 256) {
        int r = t / 182, rem = t - r * 182;
        int q = rem / 26, y = rem - q * 26;   // y-major: consecutive lanes -> consecutive y
        int x0 = q * 4;
        u64 acc01 = 0ull, acc23 = 0ull;
        const float* wr = &wd[r * 784];
#pragma unroll
        for (int js = 0; js < 8; js++) {
#pragma unroll
            for (int u = 0; u < 7; u++) {
                const u64* rp = (const u64*)&pt[(js * PWT + y + u) * PWT + x0];
                u64 P0 = rp[0], P1 = rp[1], P2 = rp[2], P3 = rp[3], P4 = rp[4];
                float p0l, p0h, p1l, p1h, p2l, p2h, p3l, p3h, p4l, p4h;
                upk2(P0, p0l, p0h); upk2(P1, p1l, p1h); upk2(P2, p2l, p2h);
                upk2(P3, p3l, p3h); upk2(P4, p4l, p4h);
                u64 O0 = pk2(p0h, p1l), O1 = pk2(p1h, p2l), O2 = pk2(p2h, p3l), O3 = pk2(p3h, p4l);
                const u64* wp = (const u64*)&wr[(js * 49 + u * 7) * 2];
                acc01 = ffma2(P0, wp[0], acc01); acc23 = ffma2(P1, wp[0], acc23);
                acc01 = ffma2(O0, wp[1], acc01); acc23 = ffma2(O1, wp[1], acc23);
                acc01 = ffma2(P1, wp[2], acc01); acc23 = ffma2(P2, wp[2], acc23);
                acc01 = ffma2(O1, wp[3], acc01); acc23 = ffma2(O2, wp[3], acc23);
                acc01 = ffma2(P2, wp[4], acc01); acc23 = ffma2(P3, wp[4], acc23);
                acc01 = ffma2(O2, wp[5], acc01); acc23 = ffma2(O3, wp[5], acc23);
                acc01 = ffma2(P3, wp[6], acc01); acc23 = ffma2(P4, wp[6], acc23);
            }
        }
        float a0, a1, a2, a3; upk2(acc01, a0, a1); upk2(acc23, a2, a3);
        float* ob = &g_att[((size_t)b * 4 + r) * H2 + y * H];
        if (x0 < H)     ob[x0]     = 1.f / (1.f + expf(-a0));
        if (x0 + 1 < H) ob[x0 + 1] = 1.f / (1.f + expf(-a1));
        if (x0 + 2 < H) ob[x0 + 2] = 1.f / (1.f + expf(-a2));
        if (x0 + 3 < H) ob[x0 + 3] = 1.f / (1.f + expf(-a3));
    }
}

// ---------------- layer-2 GG conv, y-split x3, BN0 inline, stats1 ----------------
__global__ void __launch_bounds__(192, 2) convL2(const float* __restrict__ in,
                                                 float* __restrict__ out,
                                                 const float* __restrict__ bng,
                                                 const float* __restrict__ bnb, float invN) {
    extern __shared__ float sm[];
    float* sx = sm;            // 40*10*28 = 11200 (+8 pad)
    float* sw = sm + 11208;    // 14400
    __shared__ float bsum[10], bsq[10], sc[10], sh[10];
    int b = blockIdx.x / 3, yt = blockIdx.x % 3, y0 = yt * 8;
    int tid = threadIdx.x;
    if (tid < 10) { bsum[tid] = 0.f; bsq[tid] = 0.f; }
    bn_smem(tid, 0, bng, bnb, invN, sc, sh);
    if (tid < 8) sx[11200 + tid] = 0.f;
    __syncthreads();
    const float* inb = in + (size_t)b * 27040;
    const float* attp = g_att + (size_t)b * 2704;
    for (int idx = tid; idx < 40 * 10 * 26; idx += 192) {
        int x = idx % 26; int t = idx / 26; int yy = t % 10; int is = t / 10;
        int gy = y0 + yy;
        float v = inb[is * 676 + gy * 26 + x];
        v = fmaf(v, sc[is >> 2], sh[is >> 2]);
        v = v > 0.f ? v : 0.f;
        v *= __ldg(&attp[(is & 3) * 676 + gy * 26 + x]);
        sx[(is * 10 + yy) * 28 + x] = v;
    }
    {
        const float4* wg = (const float4*)g_wc;
        float4* swv = (float4*)sw;
        for (int i = tid; i < 3600; i += 192) swv[i] = wg[i];
    }
    __syncthreads();

    float ts[10], tq[10];
#pragma unroll
    for (int o = 0; o < 10; o++) { ts[o] = 0.f; tq[o] = 0.f; }

    {
        int task = tid;
        int q = task % 6;
        int yy = (task / 6) % 8;
        int r = task / 48;
        int x0 = q * 4;
        u64 acc[4][5];
#pragma unroll
        for (int p = 0; p < 4; p++)
#pragma unroll
            for (int k = 0; k < 5; k++) acc[p][k] = 0ull;
        const float* wr = &sw[r * 3600];
        const float* xb0 = &sx[yy * 28 + x0];
        for (int is = 0; is < 40; is++) {
            const float* xb = xb0 + is * 280;
            const float* wb = wr + is * 90;
#pragma unroll
            for (int u = 0; u < 3; u++) {
                float4 v4 = *(const float4*)(xb + u * 28);
                float2 v2 = *(const float2*)(xb + u * 28 + 4);
                u64 xd[6];
                xd[0] = pk2(v4.x, v4.x); xd[1] = pk2(v4.y, v4.y);
                xd[2] = pk2(v4.z, v4.z); xd[3] = pk2(v4.w, v4.w);
                xd[4] = pk2(v2.x, v2.x); xd[5] = pk2(v2.y, v2.y);
#pragma unroll
                for (int v = 0; v < 3; v++) {
                    const u64* wp = (const u64*)(wb + u * 30 + v * 10);
#pragma unroll
                    for (int k = 0; k < 5; k++) {
                        u64 w2 = wp[k];
#pragma unroll
                        for (int p = 0; p < 4; p++)
                            acc[p][k] = ffma2(xd[v + p], w2, acc[p][k]);
                    }
                }
            }
        }
        int y = y0 + yy;
#pragma unroll
        for (int p = 0; p < 4; p++) {
            int x = x0 + p;
#pragma unroll
            for (int k = 0; k < 5; k++) {
                float lo, hi; upk2(acc[p][k], lo, hi);
                ts[2 * k] += lo;     tq[2 * k] += lo * lo;
                ts[2 * k + 1] += hi; tq[2 * k + 1] += hi * hi;
                size_t o0 = ((((size_t)b * 10 + 2 * k) * 4 + r) * 24 + y) * 24 + x;
                out[o0] = lo;
                out[o0 + (size_t)2304] = hi;
            }
        }
    }
#pragma unroll
    for (int o = 0; o < 10; o++) {
        float s = warpsum(ts[o]);
        float qv = warpsum(tq[o]);
        if ((tid & 31) == 0) { atomicAdd(&bsum[o], s); atomicAdd(&bsq[o], qv); }
    }
    __syncthreads();
    if (tid < 10) {
        atomicAdd(&g_sum[10 + tid], (double)bsum[tid]);
        atomicAdd(&g_sq[10 + tid], (double)bsq[tid]);
    }
}

// ---------------- fused layer ----------------
template <int H, int NT, int PXCH, int GIMG, bool LPOOL>
__global__ void __launch_bounds__(NT, 2) fusedgg(const float* __restrict__ in,
                                                 float* __restrict__ out,
                                                 int wlayer, int alayer, int statsIdx,
                                                 int bnIdx, const float* __restrict__ bng,
                                                 const float* __restrict__ bnb, float invN) {
    constexpr int HO = H - 2, WO = H - 2, HP = (H + 3) & ~3;
    constexpr int H2 = H * H, PLANE = H * HP;
    constexpr int NQ = (WO + PXCH - 1) / PXCH;
    constexpr int TASKS = GIMG * 4 * HO * NQ;
    constexpr int PW4R = ((H + 6) + 3) & ~3;
    constexpr int PW4 = (PW4R % 16 == 0) ? PW4R + 4 : PW4R;
    constexpr int TILE = 8 * PW4 * PW4;
    constexpr int NQA = (H + 3) / 4;
    extern __shared__ float sm[];
    float* sx = sm;
    float* sw = sm + GIMG * 40 * PLANE + 8;
    float* tile = sw;
    float* wa_s = sw + TILE + 16;
    float* att_s = wa_s + 1568;
    __shared__ float bsum[10], bsq[10], sc[10], sh[10];
    int grp = blockIdx.x, tid = threadIdx.x;
    if (tid < 10) { bsum[tid] = 0.f; bsq[tid] = 0.f; }
    bn_smem(tid, bnIdx, bng, bnb, invN, sc, sh);
    if (tid < 8) sx[GIMG * 40 * PLANE + tid] = 0.f;
    __syncthreads();

    for (int li = 0; li < GIMG; li++) {
        int b = grp * GIMG + li;
        if (LPOOL) {
            const float* inb = in + (size_t)b * 40 * 576;
            for (int idx = tid; idx < 40 * H2; idx += NT) {
                int is = idx / H2, pos = idx - is * H2;
                int y = pos / H, x = pos - y * H;
                const float* p = inb + (size_t)is * 576 + (2 * y) * 24 + 2 * x;
                float2 A = *(const float2*)p;
                float2 Bv = *(const float2*)(p + 24);
                float s = sc[is >> 2], t = sh[is >> 2];
                float v0 = fmaf(A.x, s, t), v1 = fmaf(A.y, s, t);
                float v2 = fmaf(Bv.x, s, t), v3 = fmaf(Bv.y, s, t);
                float v = fmaxf(fmaxf(v0, v1), fmaxf(v2, v3));
                v = v > 0.f ? v : 0.f;
                sx[((li * 40 + is) * H + y) * HP + x] = v;
            }
        } else {
            const float* inb = in + (size_t)b * 40 * H2;
            for (int idx = tid; idx < 40 * H2; idx += NT) {
                int is = idx / H2, pos = idx - is * H2;
                int y = pos / H, x = pos - y * H;
                float v = inb[idx];
                v = fmaf(v, sc[is >> 2], sh[is >> 2]);
                v = v > 0.f ? v : 0.f;
                sx[((li * 40 + is) * H + y) * HP + x] = v;
            }
        }
    }
    for (int i = tid; i < 1568; i += NT) wa_s[i] = g_wa[alayer * 1568 + i];
    __syncthreads();

    for (int li = 0; li < GIMG; li++) {
        for (int i = tid; i < TILE; i += NT) tile[i] = 0.f;
        __syncthreads();
        for (int idx = tid; idx < 4 * H2; idx += NT) {
            int s = idx / H2, pos = idx - s * H2;
            int y = pos / H, x = pos - y * H;
            float sum = 0.f, mx = -3.4e38f;
#pragma unroll
            for (int c = 0; c < 10; c++) {
                float v = sx[((li * 40 + c * 4 + s) * H + y) * HP + x];
                sum += v; mx = fmaxf(mx, v);
            }
            tile[(s * PW4 + y + 3) * PW4 + x + 3] = sum * 0.1f;
            tile[((4 + s) * PW4 + y + 3) * PW4 + x + 3] = mx;
        }
        __syncthreads();
        for (int t = tid; t < 4 * NQA * H; t += NT) {
            int q = t % NQA; int y = (t / NQA) % H; int r = t / (NQA * H);
            int x0 = q * 4;
            float a0 = 0.f, a1 = 0.f, a2 = 0.f, a3 = 0.f;
            const float* wb0 = &wa_s[r * 392];
#pragma unroll
            for (int js = 0; js < 8; js++) {
#pragma unroll
                for (int u = 0; u < 7; u++) {
                    const float* rowp = &tile[(js * PW4 + y + u) * PW4 + x0];
                    float4 A = *(const float4*)rowp;
                    float4 Bv = *(const float4*)(rowp + 4);
                    float2 Cv = *(const float2*)(rowp + 8);
                    float rr[10] = {A.x, A.y, A.z, A.w, Bv.x, Bv.y, Bv.z, Bv.w, Cv.x, Cv.y};
                    const float* wb = &wb0[js * 49 + u * 7];
#pragma unroll
                    for (int v = 0; v < 7; v++) {
                        float w = wb[v];
                        a0 = fmaf(rr[v], w, a0);
                        a1 = fmaf(rr[v + 1], w, a1);
                        a2 = fmaf(rr[v + 2], w, a2);
                        a3 = fmaf(rr[v + 3], w, a3);
                    }
                }
            }
            float* ob = &att_s[(li * 4 + r) * H2 + y * H];
            if (x0 < H)     ob[x0]     = 1.f / (1.f + expf(-a0));
            if (x0 + 1 < H) ob[x0 + 1] = 1.f / (1.f + expf(-a1));
            if (x0 + 2 < H) ob[x0 + 2] = 1.f / (1.f + expf(-a2));
            if (x0 + 3 < H) ob[x0 + 3] = 1.f / (1.f + expf(-a3));
        }
        __syncthreads();
    }

    for (int li = 0; li < GIMG; li++)
        for (int idx = tid; idx < 40 * H2; idx += NT) {
            int is = idx / H2, pos = idx - is * H2;
            int y = pos / H, x = pos - y * H;
            sx[((li * 40 + is) * H + y) * HP + x] *= att_s[(li * 4 + (is & 3)) * H2 + pos];
        }
    __syncthreads();
    {
        const float4* wg = (const float4*)&g_wc[wlayer * 14400];
        float4* swv = (float4*)sw;
        for (int i = tid; i < 3600; i += NT) swv[i] = wg[i];
    }
    __syncthreads();

    float ts[10], tq[10];
#pragma unroll
    for (int o = 0; o < 10; o++) { ts[o] = 0.f; tq[o] = 0.f; }

    for (int task = tid; task < TASKS; task += NT) {
        int q = task % NQ;
        int t2 = task / NQ;
        int y = t2 % HO; t2 /= HO;
        int r = t2 & 3; int li = t2 >> 2;
        int x0 = q * PXCH;
        u64 acc[PXCH][5];
#pragma unroll
        for (int p = 0; p < PXCH; p++)
#pragma unroll
            for (int k = 0; k < 5; k++) acc[p][k] = 0ull;
        const float* wr = &sw[r * 3600];
        const float* xb0 = &sx[(li * 40 * H + y) * HP + x0];
        for (int is = 0; is < 40; is++) {
            const float* xb = xb0 + is * PLANE;
            const float* wb = wr + is * 90;
#pragma unroll
            for (int u = 0; u < 3; u++) {
                u64 xd[PXCH + 2];
                if (PXCH == 4) {
                    float4 v4 = *(const float4*)(xb + u * HP);
                    float2 v2 = *(const float2*)(xb + u * HP + 4);
                    xd[0] = pk2(v4.x, v4.x); xd[1] = pk2(v4.y, v4.y);
                    xd[2] = pk2(v4.z, v4.z); xd[3] = pk2(v4.w, v4.w);
                    xd[4] = pk2(v2.x, v2.x); xd[5] = pk2(v2.y, v2.y);
                } else {
                    float2 vA = *(const float2*)(xb + u * HP);
                    float2 vB = *(const float2*)(xb + u * HP + 2);
                    xd[0] = pk2(vA.x, vA.x); xd[1] = pk2(vA.y, vA.y);
                    xd[2] = pk2(vB.x, vB.x); xd[3] = pk2(vB.y, vB.y);
                }
#pragma unroll
                for (int v = 0; v < 3; v++) {
                    const u64* wp = (const u64*)(wb + u * 30 + v * 10);
#pragma unroll
                    for (int k = 0; k < 5; k++) {
                        u64 w2 = wp[k];
#pragma unroll
                        for (int p = 0; p < PXCH; p++)
                            acc[p][k] = ffma2(xd[v + p], w2, acc[p][k]);
                    }
                }
            }
        }
        int b = grp * GIMG + li;
#pragma unroll
        for (int p = 0; p < PXCH; p++) {
            int x = x0 + p;
            if (x < WO) {
#pragma unroll
                for (int k = 0; k < 5; k++) {
                    float lo, hi; upk2(acc[p][k], lo, hi);
                    ts[2 * k] += lo;     tq[2 * k] += lo * lo;
                    ts[2 * k + 1] += hi; tq[2 * k + 1] += hi * hi;
                    size_t o0 = ((((size_t)b * 10 + 2 * k) * 4 + r) * HO + y) * WO + x;
                    out[o0] = lo;
                    out[o0 + (size_t)4 * HO * WO] = hi;
                }
            }
        }
    }
#pragma unroll
    for (int o = 0; o < 10; o++) {
        float s = warpsum(ts[o]);
        float qv = warpsum(tq[o]);
        if ((tid & 31) == 0) { atomicAdd(&bsum[o], s); atomicAdd(&bsq[o], qv); }
    }
    __syncthreads();
    if (tid < 10) {
        atomicAdd(&g_sum[statsIdx * 10 + tid], (double)bsum[tid]);
        atomicAdd(&g_sq[statsIdx * 10 + tid], (double)bsq[tid]);
    }
}

// ---------------- layer 7 fused ----------------
__global__ void __launch_bounds__(64) conv7k(const float* __restrict__ in,
                                             float* __restrict__ outp,
                                             const float* __restrict__ bng,
                                             const float* __restrict__ bnb, float invN) {
    __shared__ float sx[640], yv[40], sc[10], sh[10];
    __shared__ float tile[8 * 12 * 12 + 16];
    __shared__ float wa_s[1568];
    __shared__ float att_s[64];
    int b = blockIdx.x, tid = threadIdx.x;
    bn_smem(tid, 5, bng, bnb, invN, sc, sh);
    for (int i = tid; i < 8 * 144 + 16; i += 64) tile[i] = 0.f;
    for (int i = tid; i < 1568; i += 64) wa_s[i] = g_wa[5 * 1568 + i];
    __syncthreads();
    for (int idx = tid; idx < 640; idx += 64) {
        int c = idx >> 6;
        float v = in[(size_t)b * 640 + idx];
        v = fmaf(v, sc[c], sh[c]);
        sx[idx] = v > 0.f ? v : 0.f;
    }
    __syncthreads();
    if (tid < 64) {
        int s = tid / 16, pos = tid & 15;
        int y = pos >> 2, x = pos & 3;
        float sum = 0.f, mx = -3.4e38f;
#pragma unroll
        for (int c = 0; c < 10; c++) {
            float v = sx[(c * 4 + s) * 16 + pos];
            sum += v; mx = fmaxf(mx, v);
        }
        tile[(s * 12 + y + 3) * 12 + x + 3] = sum * 0.1f;
        tile[((4 + s) * 12 + y + 3) * 12 + x + 3] = mx;
    }
    __syncthreads();
    if (tid < 64) {
        int r = tid / 16, pos = tid & 15;
        int y = pos >> 2, x = pos & 3;
        float acc = 0.f;
        const float* wb0 = &wa_s[r * 392];
#pragma unroll
        for (int js = 0; js < 8; js++)
#pragma unroll
            for (int u = 0; u < 7; u++) {
                const float* rowp = &tile[(js * 12 + y + u) * 12 + x];
                const float* wb = &wb0[js * 49 + u * 7];
#pragma unroll
                for (int v = 0; v < 7; v++) acc = fmaf(rowp[v], wb[v], acc);
            }
        att_s[r * 16 + pos] = 1.f / (1.f + expf(-acc));
    }
    __syncthreads();
    for (int idx = tid; idx < 640; idx += 64) {
        int is = (idx >> 4) & 3;
        sx[idx] *= att_s[is * 16 + (idx & 15)];
    }
    __syncthreads();
    if (tid < 40) {
        int r = tid / 10, o = tid % 10;
        float acc = 0.f;
        for (int is = 0; is < 40; is++) {
#pragma unroll
            for (int t = 0; t < 16; t++)
                acc = fmaf(sx[is * 16 + t], __ldg(&g_wc7[((r * 40 + is) * 16 + t) * 10 + o]), acc);
        }
        yv[r * 10 + o] = acc;
    }
    __syncthreads();
    if (tid < 10) {
        float m = yv[tid];
        for (int r = 1; r < 4; r++) m = fmaxf(m, yv[r * 10 + tid]);
        outp[(size_t)b * 10 + tid] = m;
    }
}

// ---------------- launch ----------------
extern "C" void kernel_launch(void* const* d_in, const int* in_sizes, int n_in,
                              void* d_out, int out_size) {
    const float* x  = (const float*)d_in[0];
    const float* c1 = (const float*)d_in[1];
    const float* a1 = (const float*)d_in[2];
    const float* c2 = (const float*)d_in[3];
    const float* a2 = (const float*)d_in[4];
    const float* c3 = (const float*)d_in[5];
    const float* a3 = (const float*)d_in[6];
    const float* c4 = (const float*)d_in[7];
    const float* a4 = (const float*)d_in[8];
    const float* c5 = (const float*)d_in[9];
    const float* a5 = (const float*)d_in[10];
    const float* c6 = (const float*)d_in[11];
    const float* a6 = (const float*)d_in[12];
    const float* c7 = (const float*)d_in[13];
    const float* a7 = (const float*)d_in[14];
    const float* bn_g[6] = {(const float*)d_in[15], (const float*)d_in[17], (const float*)d_in[19],
                            (const float*)d_in[21], (const float*)d_in[23], (const float*)d_in[25]};
    const float* bn_b[6] = {(const float*)d_in[16], (const float*)d_in[18], (const float*)d_in[20],
                            (const float*)d_in[22], (const float*)d_in[24], (const float*)d_in[26]};
    float* out = (float*)d_out;

    int B = in_sizes[0] / 784;
    if (B > BMAX) B = BMAX;

    float *b0, *b1;
    cudaGetSymbolAddress((void**)&b0, g_buf0);
    cudaGetSymbolAddress((void**)&b1, g_buf1);

    const int SMA2 = (9248 + 3136) * 4;
    const int SML2 = (11208 + 14400) * 4;
    const int SM3 = (2 * 40 * 12 * 12 + 8 + 14400) * 4;
    const int SM4 = (2 * 40 * 10 * 12 + 8 + 14400) * 4;
    const int SM5 = (4 * 40 * 8 * 8 + 8 + 14400) * 4;
    const int SM6 = (4 * 40 * 6 * 8 + 8 + 14400) * 4;
    cudaFuncSetAttribute((const void*)attk2,  cudaFuncAttributeMaxDynamicSharedMemorySize, SMA2);
    cudaFuncSetAttribute((const void*)convL2, cudaFuncAttributeMaxDynamicSharedMemorySize, SML2);
    cudaFuncSetAttribute((const void*)fusedgg<12, 256, 4, 2, true>,  cudaFuncAttributeMaxDynamicSharedMemorySize, SM3);
    cudaFuncSetAttribute((const void*)fusedgg<10, 256, 2, 2, false>, cudaFuncAttributeMaxDynamicSharedMemorySize, SM4);
    cudaFuncSetAttribute((const void*)fusedgg<8, 288, 2, 4, false>,  cudaFuncAttributeMaxDynamicSharedMemorySize, SM5);
    cudaFuncSetAttribute((const void*)fusedgg<6, 128, 2, 4, false>,  cudaFuncAttributeMaxDynamicSharedMemorySize, SM6);

    prepk<<<64, 128>>>(c1, c2, c3, c4, c5, c6, c7, a1, a2, a3, a4, a5, a6, a7);

    l1k<<<B, 256>>>(x);

    float invN0 = 1.f / (float)(B * 4 * 676);
    {
        int tp = B * 4 * 676;
        pool26<<<(tp + 255) / 256, 256>>>(b0, B, bn_g[0], bn_b[0], invN0);
        attk2<<<B, 256, SMA2>>>();
        convL2<<<B * 3, 192, SML2>>>(b0, b1, bn_g[0], bn_b[0], invN0);
    }

    fusedgg<12, 256, 4, 2, true><<<B / 2, 256, SM3>>>(b1, b0, 1, 1, 2, 1, bn_g[1], bn_b[1], 1.f / (float)(B * 4 * 576));
    fusedgg<10, 256, 2, 2, false><<<B / 2, 256, SM4>>>(b0, b1, 2, 2, 3, 2, bn_g[2], bn_b[2], 1.f / (float)(B * 4 * 100));
    fusedgg<8, 288, 2, 4, false><<<B / 4, 288, SM5>>>(b1, b0, 3, 3, 4, 3, bn_g[3], bn_b[3], 1.f / (float)(B * 4 * 64));
    fusedgg<6, 128, 2, 4, false><<<B / 4, 128, SM6>>>(b0, b1, 4, 4, 5, 4, bn_g[4], bn_b[4], 1.f / (float)(B * 4 * 36));
    conv7k<<<B, 64>>>(b1, out, bn_g[5], bn_b[5], 1.f / (float)(B * 4 * 16));
}

// round 12
// speedup vs baseline: 1.0547x; 1.0338x over previous
#include <cuda_runtime.h>
#include <cstdint>
#include <math.h>

#define BMAX 2048
__device__ float g_buf0[BMAX * 10 * 4 * 26 * 26];
__device__ float g_buf1[BMAX * 10 * 4 * 24 * 24];
__device__ float g_att [BMAX * 4 * 26 * 26];
__device__ float g_pool[BMAX * 2 * 4 * 26 * 26];

__device__ double g_sum[60], g_sq[60];

__device__ float g_wl[4 * 3 * 3 * 10];
__device__ __align__(16) float g_wc[5 * 4 * 10 * 4 * 3 * 3 * 10];
__device__ float g_wc7[4 * 10 * 4 * 4 * 4 * 10];
__device__ float g_wa1[49];
__device__ float g_wa[6 * 4 * 2 * 4 * 7 * 7];

typedef unsigned long long u64;

__device__ __forceinline__ u64 pk2(float lo, float hi) {
    u64 r; asm("mov.b64 %0,{%1,%2};" : "=l"(r) : "f"(lo), "f"(hi)); return r;
}
__device__ __forceinline__ void upk2(u64 v, float& lo, float& hi) {
    asm("mov.b64 {%0,%1},%2;" : "=f"(lo), "=f"(hi) : "l"(v));
}
__device__ __forceinline__ u64 ffma2(u64 a, u64 b, u64 c) {
    u64 d; asm("fma.rn.f32x2 %0,%1,%2,%3;" : "=l"(d) : "l"(a), "l"(b), "l"(c)); return d;
}

__device__ __forceinline__ void rotmap(int r, int u, int v, int K, int& su, int& sv) {
    switch (r & 3) {
        case 0: su = u;         sv = v;         break;
        case 1: su = v;         sv = K - 1 - u; break;
        case 2: su = K - 1 - u; sv = K - 1 - v; break;
        default: su = K - 1 - v; sv = u;        break;
    }
}

__device__ __forceinline__ float warpsum(float v) {
    for (int o = 16; o > 0; o >>= 1) v += __shfl_down_sync(0xffffffffu, v, o);
    return v;
}

__device__ __forceinline__ void bn_smem(int tid, int bnIdx, const float* bng,
                                        const float* bnb, float invN,
                                        float* sc, float* sh) {
    if (tid < 10) {
        if (bnIdx >= 0) {
            double m = g_sum[bnIdx * 10 + tid] * (double)invN;
            double var = g_sq[bnIdx * 10 + tid] * (double)invN - m * m;
            float rstd = rsqrtf((float)var + 2e-5f);
            float s = bng[tid] * rstd;
            sc[tid] = s; sh[tid] = bnb[tid] - (float)m * s;
        } else { sc[tid] = 1.f; sh[tid] = 0.f; }
    }
}

// ---------------- prep ----------------
__global__ void prepk(const float* c1, const float* c2, const float* c3, const float* c4,
                      const float* c5, const float* c6, const float* c7,
                      const float* a1, const float* a2, const float* a3, const float* a4,
                      const float* a5, const float* a6, const float* a7) {
    int tid = blockIdx.x * blockDim.x + threadIdx.x;
    int nth = gridDim.x * blockDim.x;
    const float* cws[5] = {c2, c3, c4, c5, c6};
    const float* aws[6] = {a2, a3, a4, a5, a6, a7};

    for (int idx = tid; idx < 360; idx += nth) {
        int o = idx % 10, t = idx / 10;
        int v = t % 3; t /= 3; int u = t % 3; int r = t / 3;
        int su, sv; rotmap(r, u, v, 3, su, sv);
        g_wl[idx] = c1[o * 9 + su * 3 + sv];
    }
    for (int idx = tid; idx < 5 * 14400; idx += nth) {
        int o = idx % 10; int t = idx / 10;
        int v = t % 3; t /= 3; int u = t % 3; t /= 3;
        int s = t & 3; t >>= 2; int i = t % 10; t /= 10;
        int r = t & 3; int l = t >> 2;
        int sp = (s - r) & 3; int su, sv; rotmap(r, u, v, 3, su, sv);
        g_wc[idx] = cws[l][((o * 10 + i) * 4 + sp) * 9 + su * 3 + sv];
    }
    for (int idx = tid; idx < 25600; idx += nth) {
        int o = idx % 10; int t = idx / 10;
        int v = t & 3; t >>= 2; int u = t & 3; t >>= 2;
        int s = t & 3; t >>= 2; int i = t % 10; int r = t / 10;
        int sp = (s - r) & 3; int su, sv; rotmap(r, u, v, 4, su, sv);
        g_wc7[idx] = c7[((o * 10 + i) * 4 + sp) * 16 + su * 4 + sv];
    }
    for (int idx = tid; idx < 49; idx += nth) g_wa1[idx] = a1[idx] + a1[49 + idx];
    for (int idx = tid; idx < 6 * 1568; idx += nth) {
        int v = idx % 7; int t = idx / 7;
        int u = t % 7; t /= 7; int s = t & 3; t >>= 2;
        int i = t & 1; t >>= 1; int r = t & 3; int l = t >> 2;
        int sp = (s - r) & 3; int su, sv; rotmap(r, u, v, 7, su, sv);
        g_wa[idx] = aws[l][(i * 4 + sp) * 49 + su * 7 + sv];
    }
    for (int idx = tid; idx < 60; idx += nth) { g_sum[idx] = 0.0; g_sq[idx] = 0.0; }
}

// ---------------- layer 1: attention + gate + lifting conv + stats0 ----------------
__global__ void __launch_bounds__(256) l1k(const float* __restrict__ x) {
    __shared__ float xt[34 * 34];
    __shared__ float sxg[784];
    __shared__ float w[49];
    __shared__ float sw[360];
    __shared__ float bsum[10], bsq[10];
    int b = blockIdx.x, tid = threadIdx.x;
    for (int i = tid; i < 34 * 34; i += 256) xt[i] = 0.f;
    for (int i = tid; i < 49; i += 256) w[i] = g_wa1[i];
    for (int i = tid; i < 360; i += 256) sw[i] = g_wl[i];
    if (tid < 10) { bsum[tid] = 0.f; bsq[tid] = 0.f; }
    __syncthreads();
    for (int i = tid; i < 784; i += 256) {
        int y = i / 28, xx = i % 28;
        xt[(y + 3) * 34 + xx + 3] = x[(size_t)b * 784 + i];
    }
    __syncthreads();
    for (int p = tid; p < 784; p += 256) {
        int y = p / 28, xx = p % 28;
        float acc = 0.f;
#pragma unroll
        for (int u = 0; u < 7; u++)
#pragma unroll
            for (int v = 0; v < 7; v++)
                acc = fmaf(xt[(y + u) * 34 + xx + v], w[u * 7 + v], acc);
        float xv = xt[(y + 3) * 34 + xx + 3];
        sxg[p] = xv * (1.f / (1.f + expf(-acc)));
    }
    __syncthreads();
    float ts[10], tq[10];
#pragma unroll
    for (int o = 0; o < 10; o++) { ts[o] = 0.f; tq[o] = 0.f; }
    for (int r = 0; r < 4; r++) {
        for (int pp = tid; pp < 338; pp += 256) {
            int y = pp / 13, x0 = (pp % 13) * 2;
            float a0[10], a1[10];
#pragma unroll
            for (int o = 0; o < 10; o++) { a0[o] = 0.f; a1[o] = 0.f; }
#pragma unroll
            for (int u = 0; u < 3; u++)
#pragma unroll
                for (int v = 0; v < 3; v++) {
                    float xv0 = sxg[(y + u) * 28 + x0 + v];
                    float xv1 = sxg[(y + u) * 28 + x0 + v + 1];
                    const float* wp = &sw[((r * 3 + u) * 3 + v) * 10];
#pragma unroll
                    for (int o = 0; o < 10; o++) {
                        a0[o] = fmaf(xv0, wp[o], a0[o]);
                        a1[o] = fmaf(xv1, wp[o], a1[o]);
                    }
                }
#pragma unroll
            for (int o = 0; o < 10; o++) {
                size_t off = ((((size_t)b * 10 + o) * 4 + r) * 26 + y) * 26 + x0;
                g_buf0[off] = a0[o]; g_buf0[off + 1] = a1[o];
                ts[o] += a0[o] + a1[o];
                tq[o] += a0[o] * a0[o] + a1[o] * a1[o];
            }
        }
    }
#pragma unroll
    for (int o = 0; o < 10; o++) {
        float s = warpsum(ts[o]);
        float q = warpsum(tq[o]);
        if ((tid & 31) == 0) { atomicAdd(&bsum[o], s); atomicAdd(&bsq[o], q); }
    }
    __syncthreads();
    if (tid < 10) {
        atomicAdd(&g_sum[tid], (double)bsum[tid]);
        atomicAdd(&g_sq[tid], (double)bsq[tid]);
    }
}

// ---------------- layer-2 pooled (mean,max) with BN0 inline ----------------
__global__ void __launch_bounds__(256) pool26(const float* __restrict__ in, int B,
                                              const float* __restrict__ bng,
                                              const float* __restrict__ bnb, float invN) {
    const int H2 = 676;
    __shared__ float sc[10], sh[10];
    bn_smem(threadIdx.x, 0, bng, bnb, invN, sc, sh);
    __syncthreads();
    int total = B * 4 * H2;
    for (int idx = blockIdx.x * blockDim.x + threadIdx.x; idx < total;
         idx += gridDim.x * blockDim.x) {
        int pos = idx % H2;
        int s = (idx / H2) & 3;
        int b = idx / (4 * H2);
        const float* p = in + ((size_t)b * 40 + s) * H2 + pos;
        float sum = 0.f, mx = -3.4e38f;
#pragma unroll
        for (int c = 0; c < 10; c++) {
            float v = fmaf(p[(size_t)c * 4 * H2], sc[c], sh[c]);
            v = v > 0.f ? v : 0.f;
            sum += v; mx = fmaxf(mx, v);
        }
        g_pool[((size_t)b * 8 + s) * H2 + pos]     = sum * 0.1f;
        g_pool[((size_t)b * 8 + 4 + s) * H2 + pos] = mx;
    }
}

// ---------------- layer-2 GG attention conv: full-row register blocking ----------
// One task = (image, rotation, output row). 13 f32x2 accumulators cover all 26
// pixels; per (js,u) tap-row: 16 LDS.64 row + 7 LDS.64 weights for 91 ffma2.
// Block = 2 images (tile built once, shared by all 4 rotations).
__global__ void __launch_bounds__(256) attk2() {
    constexpr int H = 26, H2 = 676, PWT = 34;
    extern __shared__ __align__(16) float dsm[];
    float* wd = dsm;                 // 3136 (duplicated weights, 4 rotations)
    float* pt = dsm + 3136;          // 2 * 8*34*34 = 18496
    int bb = blockIdx.x * 2, tid = threadIdx.x;
    for (int i = tid; i < 1568; i += 256) {
        float w = g_wa[i];
        wd[2 * i] = w; wd[2 * i + 1] = w;
    }
    for (int i = tid; i < 2 * 9248; i += 256) pt[i] = 0.f;
    __syncthreads();
    for (int li = 0; li < 2; li++) {
        const float* pb = g_pool + (size_t)(bb + li) * 8 * H2;
        for (int idx = tid; idx < 8 * H2; idx += 256) {
            int js = idx / H2, pos = idx - js * H2;
            int y = pos / H, x = pos - y * H;
            pt[li * 9248 + (js * PWT + y + 3) * PWT + x + 3] = pb[idx];
        }
    }
    __syncthreads();
    // 208 tasks: li(2) x r(4) x y(26); y fastest so warp lanes hit distinct banks
    if (tid < 208) {
        int li = tid / 104; int rem = tid - li * 104;
        int r = rem / 26, y = rem - r * 26;
        u64 acc[13];
#pragma unroll
        for (int i = 0; i < 13; i++) acc[i] = 0ull;
        const float* base = pt + li * 9248;
        const u64* wr = (const u64*)&wd[r * 784];
        for (int js = 0; js < 8; js++) {
#pragma unroll
            for (int u = 0; u < 7; u++) {
                const u64* rp = (const u64*)&base[(js * PWT + y + u) * PWT];
                u64 P[16];
#pragma unroll
                for (int k = 0; k < 16; k++) P[k] = rp[k];
                float f[32];
#pragma unroll
                for (int k = 0; k < 16; k++) upk2(P[k], f[2 * k], f[2 * k + 1]);
                u64 O[15];
#pragma unroll
                for (int k = 0; k < 15; k++) O[k] = pk2(f[2 * k + 1], f[2 * k + 2]);
                const u64* wp = wr + (js * 49 + u * 7);
#pragma unroll
                for (int v = 0; v < 7; v++) {
                    u64 w2 = wp[v];
                    if ((v & 1) == 0) {
#pragma unroll
                        for (int i = 0; i < 13; i++)
                            acc[i] = ffma2(P[i + v / 2], w2, acc[i]);
                    } else {
#pragma unroll
                        for (int i = 0; i < 13; i++)
                            acc[i] = ffma2(O[i + (v - 1) / 2], w2, acc[i]);
                    }
                }
            }
        }
        float* ob = &g_att[((size_t)(bb + li) * 4 + r) * H2 + y * H];
#pragma unroll
        for (int i = 0; i < 13; i++) {
            float a0, a1; upk2(acc[i], a0, a1);
            ob[2 * i]     = 1.f / (1.f + expf(-a0));
            ob[2 * i + 1] = 1.f / (1.f + expf(-a1));
        }
    }
}

// ---------------- layer-2 GG conv, y-split x3, BN0 inline, stats1 ----------------
__global__ void __launch_bounds__(192, 2) convL2(const float* __restrict__ in,
                                                 float* __restrict__ out,
                                                 const float* __restrict__ bng,
                                                 const float* __restrict__ bnb, float invN) {
    extern __shared__ float sm[];
    float* sx = sm;            // 40*10*28 = 11200 (+8 pad)
    float* sw = sm + 11208;    // 14400
    __shared__ float bsum[10], bsq[10], sc[10], sh[10];
    int b = blockIdx.x / 3, yt = blockIdx.x % 3, y0 = yt * 8;
    int tid = threadIdx.x;
    if (tid < 10) { bsum[tid] = 0.f; bsq[tid] = 0.f; }
    bn_smem(tid, 0, bng, bnb, invN, sc, sh);
    if (tid < 8) sx[11200 + tid] = 0.f;
    __syncthreads();
    const float* inb = in + (size_t)b * 27040;
    const float* attp = g_att + (size_t)b * 2704;
    for (int idx = tid; idx < 40 * 10 * 26; idx += 192) {
        int x = idx % 26; int t = idx / 26; int yy = t % 10; int is = t / 10;
        int gy = y0 + yy;
        float v = inb[is * 676 + gy * 26 + x];
        v = fmaf(v, sc[is >> 2], sh[is >> 2]);
        v = v > 0.f ? v : 0.f;
        v *= __ldg(&attp[(is & 3) * 676 + gy * 26 + x]);
        sx[(is * 10 + yy) * 28 + x] = v;
    }
    {
        const float4* wg = (const float4*)g_wc;
        float4* swv = (float4*)sw;
        for (int i = tid; i < 3600; i += 192) swv[i] = wg[i];
    }
    __syncthreads();

    float ts[10], tq[10];
#pragma unroll
    for (int o = 0; o < 10; o++) { ts[o] = 0.f; tq[o] = 0.f; }

    {
        int task = tid;
        int q = task % 6;
        int yy = (task / 6) % 8;
        int r = task / 48;
        int x0 = q * 4;
        u64 acc[4][5];
#pragma unroll
        for (int p = 0; p < 4; p++)
#pragma unroll
            for (int k = 0; k < 5; k++) acc[p][k] = 0ull;
        const float* wr = &sw[r * 3600];
        const float* xb0 = &sx[yy * 28 + x0];
        for (int is = 0; is < 40; is++) {
            const float* xb = xb0 + is * 280;
            const float* wb = wr + is * 90;
#pragma unroll
            for (int u = 0; u < 3; u++) {
                float4 v4 = *(const float4*)(xb + u * 28);
                float2 v2 = *(const float2*)(xb + u * 28 + 4);
                u64 xd[6];
                xd[0] = pk2(v4.x, v4.x); xd[1] = pk2(v4.y, v4.y);
                xd[2] = pk2(v4.z, v4.z); xd[3] = pk2(v4.w, v4.w);
                xd[4] = pk2(v2.x, v2.x); xd[5] = pk2(v2.y, v2.y);
#pragma unroll
                for (int v = 0; v < 3; v++) {
                    const u64* wp = (const u64*)(wb + u * 30 + v * 10);
#pragma unroll
                    for (int k = 0; k < 5; k++) {
                        u64 w2 = wp[k];
#pragma unroll
                        for (int p = 0; p < 4; p++)
                            acc[p][k] = ffma2(xd[v + p], w2, acc[p][k]);
                    }
                }
            }
        }
        int y = y0 + yy;
#pragma unroll
        for (int p = 0; p < 4; p++) {
            int x = x0 + p;
#pragma unroll
            for (int k = 0; k < 5; k++) {
                float lo, hi; upk2(acc[p][k], lo, hi);
                ts[2 * k] += lo;     tq[2 * k] += lo * lo;
                ts[2 * k + 1] += hi; tq[2 * k + 1] += hi * hi;
                size_t o0 = ((((size_t)b * 10 + 2 * k) * 4 + r) * 24 + y) * 24 + x;
                out[o0] = lo;
                out[o0 + (size_t)2304] = hi;
            }
        }
    }
#pragma unroll
    for (int o = 0; o < 10; o++) {
        float s = warpsum(ts[o]);
        float qv = warpsum(tq[o]);
        if ((tid & 31) == 0) { atomicAdd(&bsum[o], s); atomicAdd(&bsq[o], qv); }
    }
    __syncthreads();
    if (tid < 10) {
        atomicAdd(&g_sum[10 + tid], (double)bsum[tid]);
        atomicAdd(&g_sq[10 + tid], (double)bsq[tid]);
    }
}

// ---------------- fused layer ----------------
template <int H, int NT, int PXCH, int GIMG, bool LPOOL>
__global__ void __launch_bounds__(NT, 2) fusedgg(const float* __restrict__ in,
                                                 float* __restrict__ out,
                                                 int wlayer, int alayer, int statsIdx,
                                                 int bnIdx, const float* __restrict__ bng,
                                                 const float* __restrict__ bnb, float invN) {
    constexpr int HO = H - 2, WO = H - 2, HP = (H + 3) & ~3;
    constexpr int H2 = H * H, PLANE = H * HP;
    constexpr int NQ = (WO + PXCH - 1) / PXCH;
    constexpr int TASKS = GIMG * 4 * HO * NQ;
    constexpr int PW4R = ((H + 6) + 3) & ~3;
    constexpr int PW4 = (PW4R % 16 == 0) ? PW4R + 4 : PW4R;
    constexpr int TILE = 8 * PW4 * PW4;
    constexpr int NQA = (H + 3) / 4;
    extern __shared__ float sm[];
    float* sx = sm;
    float* sw = sm + GIMG * 40 * PLANE + 8;
    float* tile = sw;
    float* wa_s = sw + TILE + 16;
    float* att_s = wa_s + 1568;
    __shared__ float bsum[10], bsq[10], sc[10], sh[10];
    int grp = blockIdx.x, tid = threadIdx.x;
    if (tid < 10) { bsum[tid] = 0.f; bsq[tid] = 0.f; }
    bn_smem(tid, bnIdx, bng, bnb, invN, sc, sh);
    if (tid < 8) sx[GIMG * 40 * PLANE + tid] = 0.f;
    __syncthreads();

    for (int li = 0; li < GIMG; li++) {
        int b = grp * GIMG + li;
        if (LPOOL) {
            const float* inb = in + (size_t)b * 40 * 576;
            for (int idx = tid; idx < 40 * H2; idx += NT) {
                int is = idx / H2, pos = idx - is * H2;
                int y = pos / H, x = pos - y * H;
                const float* p = inb + (size_t)is * 576 + (2 * y) * 24 + 2 * x;
                float2 A = *(const float2*)p;
                float2 Bv = *(const float2*)(p + 24);
                float s = sc[is >> 2], t = sh[is >> 2];
                float v0 = fmaf(A.x, s, t), v1 = fmaf(A.y, s, t);
                float v2 = fmaf(Bv.x, s, t), v3 = fmaf(Bv.y, s, t);
                float v = fmaxf(fmaxf(v0, v1), fmaxf(v2, v3));
                v = v > 0.f ? v : 0.f;
                sx[((li * 40 + is) * H + y) * HP + x] = v;
            }
        } else {
            const float* inb = in + (size_t)b * 40 * H2;
            for (int idx = tid; idx < 40 * H2; idx += NT) {
                int is = idx / H2, pos = idx - is * H2;
                int y = pos / H, x = pos - y * H;
                float v = inb[idx];
                v = fmaf(v, sc[is >> 2], sh[is >> 2]);
                v = v > 0.f ? v : 0.f;
                sx[((li * 40 + is) * H + y) * HP + x] = v;
            }
        }
    }
    for (int i = tid; i < 1568; i += NT) wa_s[i] = g_wa[alayer * 1568 + i];
    __syncthreads();

    for (int li = 0; li < GIMG; li++) {
        for (int i = tid; i < TILE; i += NT) tile[i] = 0.f;
        __syncthreads();
        for (int idx = tid; idx < 4 * H2; idx += NT) {
            int s = idx / H2, pos = idx - s * H2;
            int y = pos / H, x = pos - y * H;
            float sum = 0.f, mx = -3.4e38f;
#pragma unroll
            for (int c = 0; c < 10; c++) {
                float v = sx[((li * 40 + c * 4 + s) * H + y) * HP + x];
                sum += v; mx = fmaxf(mx, v);
            }
            tile[(s * PW4 + y + 3) * PW4 + x + 3] = sum * 0.1f;
            tile[((4 + s) * PW4 + y + 3) * PW4 + x + 3] = mx;
        }
        __syncthreads();
        for (int t = tid; t < 4 * NQA * H; t += NT) {
            int q = t % NQA; int y = (t / NQA) % H; int r = t / (NQA * H);
            int x0 = q * 4;
            float a0 = 0.f, a1 = 0.f, a2 = 0.f, a3 = 0.f;
            const float* wb0 = &wa_s[r * 392];
#pragma unroll
            for (int js = 0; js < 8; js++) {
#pragma unroll
                for (int u = 0; u < 7; u++) {
                    const float* rowp = &tile[(js * PW4 + y + u) * PW4 + x0];
                    float4 A = *(const float4*)rowp;
                    float4 Bv = *(const float4*)(rowp + 4);
                    float2 Cv = *(const float2*)(rowp + 8);
                    float rr[10] = {A.x, A.y, A.z, A.w, Bv.x, Bv.y, Bv.z, Bv.w, Cv.x, Cv.y};
                    const float* wb = &wb0[js * 49 + u * 7];
#pragma unroll
                    for (int v = 0; v < 7; v++) {
                        float w = wb[v];
                        a0 = fmaf(rr[v], w, a0);
                        a1 = fmaf(rr[v + 1], w, a1);
                        a2 = fmaf(rr[v + 2], w, a2);
                        a3 = fmaf(rr[v + 3], w, a3);
                    }
                }
            }
            float* ob = &att_s[(li * 4 + r) * H2 + y * H];
            if (x0 < H)     ob[x0]     = 1.f / (1.f + expf(-a0));
            if (x0 + 1 < H) ob[x0 + 1] = 1.f / (1.f + expf(-a1));
            if (x0 + 2 < H) ob[x0 + 2] = 1.f / (1.f + expf(-a2));
            if (x0 + 3 < H) ob[x0 + 3] = 1.f / (1.f + expf(-a3));
        }
        __syncthreads();
    }

    for (int li = 0; li < GIMG; li++)
        for (int idx = tid; idx < 40 * H2; idx += NT) {
            int is = idx / H2, pos = idx - is * H2;
            int y = pos / H, x = pos - y * H;
            sx[((li * 40 + is) * H + y) * HP + x] *= att_s[(li * 4 + (is & 3)) * H2 + pos];
        }
    __syncthreads();
    {
        const float4* wg = (const float4*)&g_wc[wlayer * 14400];
        float4* swv = (float4*)sw;
        for (int i = tid; i < 3600; i += NT) swv[i] = wg[i];
    }
    __syncthreads();

    float ts[10], tq[10];
#pragma unroll
    for (int o = 0; o < 10; o++) { ts[o] = 0.f; tq[o] = 0.f; }

    for (int task = tid; task < TASKS; task += NT) {
        int q = task % NQ;
        int t2 = task / NQ;
        int y = t2 % HO; t2 /= HO;
        int r = t2 & 3; int li = t2 >> 2;
        int x0 = q * PXCH;
        u64 acc[PXCH][5];
#pragma unroll
        for (int p = 0; p < PXCH; p++)
#pragma unroll
            for (int k = 0; k < 5; k++) acc[p][k] = 0ull;
        const float* wr = &sw[r * 3600];
        const float* xb0 = &sx[(li * 40 * H + y) * HP + x0];
        for (int is = 0; is < 40; is++) {
            const float* xb = xb0 + is * PLANE;
            const float* wb = wr + is * 90;
#pragma unroll
            for (int u = 0; u < 3; u++) {
                u64 xd[PXCH + 2];
                if (PXCH == 4) {
                    float4 v4 = *(const float4*)(xb + u * HP);
                    float2 v2 = *(const float2*)(xb + u * HP + 4);
                    xd[0] = pk2(v4.x, v4.x); xd[1] = pk2(v4.y, v4.y);
                    xd[2] = pk2(v4.z, v4.z); xd[3] = pk2(v4.w, v4.w);
                    xd[4] = pk2(v2.x, v2.x); xd[5] = pk2(v2.y, v2.y);
                } else {
                    float2 vA = *(const float2*)(xb + u * HP);
                    float2 vB = *(const float2*)(xb + u * HP + 2);
                    xd[0] = pk2(vA.x, vA.x); xd[1] = pk2(vA.y, vA.y);
                    xd[2] = pk2(vB.x, vB.x); xd[3] = pk2(vB.y, vB.y);
                }
#pragma unroll
                for (int v = 0; v < 3; v++) {
                    const u64* wp = (const u64*)(wb + u * 30 + v * 10);
#pragma unroll
                    for (int k = 0; k < 5; k++) {
                        u64 w2 = wp[k];
#pragma unroll
                        for (int p = 0; p < PXCH; p++)
                            acc[p][k] = ffma2(xd[v + p], w2, acc[p][k]);
                    }
                }
            }
        }
        int b = grp * GIMG + li;
#pragma unroll
        for (int p = 0; p < PXCH; p++) {
            int x = x0 + p;
            if (x < WO) {
#pragma unroll
                for (int k = 0; k < 5; k++) {
                    float lo, hi; upk2(acc[p][k], lo, hi);
                    ts[2 * k] += lo;     tq[2 * k] += lo * lo;
                    ts[2 * k + 1] += hi; tq[2 * k + 1] += hi * hi;
                    size_t o0 = ((((size_t)b * 10 + 2 * k) * 4 + r) * HO + y) * WO + x;
                    out[o0] = lo;
                    out[o0 + (size_t)4 * HO * WO] = hi;
                }
            }
        }
    }
#pragma unroll
    for (int o = 0; o < 10; o++) {
        float s = warpsum(ts[o]);
        float qv = warpsum(tq[o]);
        if ((tid & 31) == 0) { atomicAdd(&bsum[o], s); atomicAdd(&bsq[o], qv); }
    }
    __syncthreads();
    if (tid < 10) {
        atomicAdd(&g_sum[statsIdx * 10 + tid], (double)bsum[tid]);
        atomicAdd(&g_sq[statsIdx * 10 + tid], (double)bsq[tid]);
    }
}

// ---------------- layer 7 fused ----------------
__global__ void __launch_bounds__(64) conv7k(const float* __restrict__ in,
                                             float* __restrict__ outp,
                                             const float* __restrict__ bng,
                                             const float* __restrict__ bnb, float invN) {
    __shared__ float sx[640], yv[40], sc[10], sh[10];
    __shared__ float tile[8 * 12 * 12 + 16];
    __shared__ float wa_s[1568];
    __shared__ float att_s[64];
    int b = blockIdx.x, tid = threadIdx.x;
    bn_smem(tid, 5, bng, bnb, invN, sc, sh);
    for (int i = tid; i < 8 * 144 + 16; i += 64) tile[i] = 0.f;
    for (int i = tid; i < 1568; i += 64) wa_s[i] = g_wa[5 * 1568 + i];
    __syncthreads();
    for (int idx = tid; idx < 640; idx += 64) {
        int c = idx >> 6;
        float v = in[(size_t)b * 640 + idx];
        v = fmaf(v, sc[c], sh[c]);
        sx[idx] = v > 0.f ? v : 0.f;
    }
    __syncthreads();
    if (tid < 64) {
        int s = tid / 16, pos = tid & 15;
        int y = pos >> 2, x = pos & 3;
        float sum = 0.f, mx = -3.4e38f;
#pragma unroll
        for (int c = 0; c < 10; c++) {
            float v = sx[(c * 4 + s) * 16 + pos];
            sum += v; mx = fmaxf(mx, v);
        }
        tile[(s * 12 + y + 3) * 12 + x + 3] = sum * 0.1f;
        tile[((4 + s) * 12 + y + 3) * 12 + x + 3] = mx;
    }
    __syncthreads();
    if (tid < 64) {
        int r = tid / 16, pos = tid & 15;
        int y = pos >> 2, x = pos & 3;
        float acc = 0.f;
        const float* wb0 = &wa_s[r * 392];
#pragma unroll
        for (int js = 0; js < 8; js++)
#pragma unroll
            for (int u = 0; u < 7; u++) {
                const float* rowp = &tile[(js * 12 + y + u) * 12 + x];
                const float* wb = &wb0[js * 49 + u * 7];
#pragma unroll
                for (int v = 0; v < 7; v++) acc = fmaf(rowp[v], wb[v], acc);
            }
        att_s[r * 16 + pos] = 1.f / (1.f + expf(-acc));
    }
    __syncthreads();
    for (int idx = tid; idx < 640; idx += 64) {
        int is = (idx >> 4) & 3;
        sx[idx] *= att_s[is * 16 + (idx & 15)];
    }
    __syncthreads();
    if (tid < 40) {
        int r = tid / 10, o = tid % 10;
        float acc = 0.f;
        for (int is = 0; is < 40; is++) {
#pragma unroll
            for (int t = 0; t < 16; t++)
                acc = fmaf(sx[is * 16 + t], __ldg(&g_wc7[((r * 40 + is) * 16 + t) * 10 + o]), acc);
        }
        yv[r * 10 + o] = acc;
    }
    __syncthreads();
    if (tid < 10) {
        float m = yv[tid];
        for (int r = 1; r < 4; r++) m = fmaxf(m, yv[r * 10 + tid]);
        outp[(size_t)b * 10 + tid] = m;
    }
}

// ---------------- launch ----------------
extern "C" void kernel_launch(void* const* d_in, const int* in_sizes, int n_in,
                              void* d_out, int out_size) {
    const float* x  = (const float*)d_in[0];
    const float* c1 = (const float*)d_in[1];
    const float* a1 = (const float*)d_in[2];
    const float* c2 = (const float*)d_in[3];
    const float* a2 = (const float*)d_in[4];
    const float* c3 = (const float*)d_in[5];
    const float* a3 = (const float*)d_in[6];
    const float* c4 = (const float*)d_in[7];
    const float* a4 = (const float*)d_in[8];
    const float* c5 = (const float*)d_in[9];
    const float* a5 = (const float*)d_in[10];
    const float* c6 = (const float*)d_in[11];
    const float* a6 = (const float*)d_in[12];
    const float* c7 = (const float*)d_in[13];
    const float* a7 = (const float*)d_in[14];
    const float* bn_g[6] = {(const float*)d_in[15], (const float*)d_in[17], (const float*)d_in[19],
                            (const float*)d_in[21], (const float*)d_in[23], (const float*)d_in[25]};
    const float* bn_b[6] = {(const float*)d_in[16], (const float*)d_in[18], (const float*)d_in[20],
                            (const float*)d_in[22], (const float*)d_in[24], (const float*)d_in[26]};
    float* out = (float*)d_out;

    int B = in_sizes[0] / 784;
    if (B > BMAX) B = BMAX;

    float *b0, *b1;
    cudaGetSymbolAddress((void**)&b0, g_buf0);
    cudaGetSymbolAddress((void**)&b1, g_buf1);

    const int SMA2 = (3136 + 2 * 9248) * 4;
    const int SML2 = (11208 + 14400) * 4;
    const int SM3 = (2 * 40 * 12 * 12 + 8 + 14400) * 4;
    const int SM4 = (2 * 40 * 10 * 12 + 8 + 14400) * 4;
    const int SM5 = (4 * 40 * 8 * 8 + 8 + 14400) * 4;
    const int SM6 = (4 * 40 * 6 * 8 + 8 + 14400) * 4;
    cudaFuncSetAttribute((const void*)attk2,  cudaFuncAttributeMaxDynamicSharedMemorySize, SMA2);
    cudaFuncSetAttribute((const void*)convL2, cudaFuncAttributeMaxDynamicSharedMemorySize, SML2);
    cudaFuncSetAttribute((const void*)fusedgg<12, 256, 4, 2, true>,  cudaFuncAttributeMaxDynamicSharedMemorySize, SM3);
    cudaFuncSetAttribute((const void*)fusedgg<10, 256, 2, 2, false>, cudaFuncAttributeMaxDynamicSharedMemorySize, SM4);
    cudaFuncSetAttribute((const void*)fusedgg<8, 288, 2, 4, false>,  cudaFuncAttributeMaxDynamicSharedMemorySize, SM5);
    cudaFuncSetAttribute((const void*)fusedgg<6, 128, 2, 4, false>,  cudaFuncAttributeMaxDynamicSharedMemorySize, SM6);

    prepk<<<64, 128>>>(c1, c2, c3, c4, c5, c6, c7, a1, a2, a3, a4, a5, a6, a7);

    l1k<<<B, 256>>>(x);

    float invN0 = 1.f / (float)(B * 4 * 676);
    {
        int tp = B * 4 * 676;
        pool26<<<(tp + 255) / 256, 256>>>(b0, B, bn_g[0], bn_b[0], invN0);
        attk2<<<B / 2, 256, SMA2>>>();
        convL2<<<B * 3, 192, SML2>>>(b0, b1, bn_g[0], bn_b[0], invN0);
    }

    fusedgg<12, 256, 4, 2, true><<<B / 2, 256, SM3>>>(b1, b0, 1, 1, 2, 1, bn_g[1], bn_b[1], 1.f / (float)(B * 4 * 576));
    fusedgg<10, 256, 2, 2, false><<<B / 2, 256, SM4>>>(b0, b1, 2, 2, 3, 2, bn_g[2], bn_b[2], 1.f / (float)(B * 4 * 100));
    fusedgg<8, 288, 2, 4, false><<<B / 4, 288, SM5>>>(b1, b0, 3, 3, 4, 3, bn_g[3], bn_b[3], 1.f / (float)(B * 4 * 64));
    fusedgg<6, 128, 2, 4, false><<<B / 4, 128, SM6>>>(b0, b1, 4, 4, 5, 4, bn_g[4], bn_b[4], 1.f / (float)(B * 4 * 36));
    conv7k<<<B, 64>>>(b1, out, bn_g[5], bn_b[5], 1.f / (float)(B * 4 * 16));
}

// round 14
// speedup vs baseline: 1.0702x; 1.0147x over previous
#include <cuda_runtime.h>
#include <cstdint>
#include <math.h>

#define BMAX 2048
__device__ float g_buf0[BMAX * 10 * 4 * 26 * 26];
__device__ float g_buf1[BMAX * 10 * 4 * 24 * 24];
__device__ float g_att [BMAX * 4 * 26 * 26];

__device__ double g_sum[60], g_sq[60];

__device__ float g_wl[4 * 3 * 3 * 10];
__device__ __align__(16) float g_wc[5 * 4 * 10 * 4 * 3 * 3 * 10];
__device__ float g_wc7[4 * 10 * 4 * 4 * 4 * 10];
__device__ float g_wa1[49];
__device__ float g_wa[6 * 4 * 2 * 4 * 7 * 7];

typedef unsigned long long u64;

__device__ __forceinline__ u64 pk2(float lo, float hi) {
    u64 r; asm("mov.b64 %0,{%1,%2};" : "=l"(r) : "f"(lo), "f"(hi)); return r;
}
__device__ __forceinline__ void upk2(u64 v, float& lo, float& hi) {
    asm("mov.b64 {%0,%1},%2;" : "=f"(lo), "=f"(hi) : "l"(v));
}
__device__ __forceinline__ u64 ffma2(u64 a, u64 b, u64 c) {
    u64 d; asm("fma.rn.f32x2 %0,%1,%2,%3;" : "=l"(d) : "l"(a), "l"(b), "l"(c)); return d;
}

__device__ __forceinline__ void rotmap(int r, int u, int v, int K, int& su, int& sv) {
    switch (r & 3) {
        case 0: su = u;         sv = v;         break;
        case 1: su = v;         sv = K - 1 - u; break;
        case 2: su = K - 1 - u; sv = K - 1 - v; break;
        default: su = K - 1 - v; sv = u;        break;
    }
}

__device__ __forceinline__ float warpsum(float v) {
    for (int o = 16; o > 0; o >>= 1) v += __shfl_down_sync(0xffffffffu, v, o);
    return v;
}

__device__ __forceinline__ void bn_smem(int tid, int bnIdx, const float* bng,
                                        const float* bnb, float invN,
                                        float* sc, float* sh) {
    if (tid < 10) {
        if (bnIdx >= 0) {
            double m = g_sum[bnIdx * 10 + tid] * (double)invN;
            double var = g_sq[bnIdx * 10 + tid] * (double)invN - m * m;
            float rstd = rsqrtf((float)var + 2e-5f);
            float s = bng[tid] * rstd;
            sc[tid] = s; sh[tid] = bnb[tid] - (float)m * s;
        } else { sc[tid] = 1.f; sh[tid] = 0.f; }
    }
}

// ---------------- prep ----------------
__global__ void prepk(const float* c1, const float* c2, const float* c3, const float* c4,
                      const float* c5, const float* c6, const float* c7,
                      const float* a1, const float* a2, const float* a3, const float* a4,
                      const float* a5, const float* a6, const float* a7) {
    int tid = blockIdx.x * blockDim.x + threadIdx.x;
    int nth = gridDim.x * blockDim.x;
    const float* cws[5] = {c2, c3, c4, c5, c6};
    const float* aws[6] = {a2, a3, a4, a5, a6, a7};

    for (int idx = tid; idx < 360; idx += nth) {
        int o = idx % 10, t = idx / 10;
        int v = t % 3; t /= 3; int u = t % 3; int r = t / 3;
        int su, sv; rotmap(r, u, v, 3, su, sv);
        g_wl[idx] = c1[o * 9 + su * 3 + sv];
    }
    for (int idx = tid; idx < 5 * 14400; idx += nth) {
        int o = idx % 10; int t = idx / 10;
        int v = t % 3; t /= 3; int u = t % 3; t /= 3;
        int s = t & 3; t >>= 2; int i = t % 10; t /= 10;
        int r = t & 3; int l = t >> 2;
        int sp = (s - r) & 3; int su, sv; rotmap(r, u, v, 3, su, sv);
        g_wc[idx] = cws[l][((o * 10 + i) * 4 + sp) * 9 + su * 3 + sv];
    }
    for (int idx = tid; idx < 25600; idx += nth) {
        int o = idx % 10; int t = idx / 10;
        int v = t & 3; t >>= 2; int u = t & 3; t >>= 2;
        int s = t & 3; t >>= 2; int i = t % 10; int r = t / 10;
        int sp = (s - r) & 3; int su, sv; rotmap(r, u, v, 4, su, sv);
        g_wc7[idx] = c7[((o * 10 + i) * 4 + sp) * 16 + su * 4 + sv];
    }
    for (int idx = tid; idx < 49; idx += nth) g_wa1[idx] = a1[idx] + a1[49 + idx];
    for (int idx = tid; idx < 6 * 1568; idx += nth) {
        int v = idx % 7; int t = idx / 7;
        int u = t % 7; t /= 7; int s = t & 3; t >>= 2;
        int i = t & 1; t >>= 1; int r = t & 3; int l = t >> 2;
        int sp = (s - r) & 3; int su, sv; rotmap(r, u, v, 7, su, sv);
        g_wa[idx] = aws[l][(i * 4 + sp) * 49 + su * 7 + sv];
    }
    for (int idx = tid; idx < 60; idx += nth) { g_sum[idx] = 0.0; g_sq[idx] = 0.0; }
}

// ---------------- layer 1: attention + gate + lifting conv + stats0 ----------------
__global__ void __launch_bounds__(256) l1k(const float* __restrict__ x) {
    __shared__ float xt[34 * 34];
    __shared__ float sxg[784];
    __shared__ float w[49];
    __shared__ float sw[360];
    __shared__ float bsum[10], bsq[10];
    int b = blockIdx.x, tid = threadIdx.x;
    for (int i = tid; i < 34 * 34; i += 256) xt[i] = 0.f;
    for (int i = tid; i < 49; i += 256) w[i] = g_wa1[i];
    for (int i = tid; i < 360; i += 256) sw[i] = g_wl[i];
    if (tid < 10) { bsum[tid] = 0.f; bsq[tid] = 0.f; }
    __syncthreads();
    for (int i = tid; i < 784; i += 256) {
        int y = i / 28, xx = i % 28;
        xt[(y + 3) * 34 + xx + 3] = x[(size_t)b * 784 + i];
    }
    __syncthreads();
    for (int p = tid; p < 784; p += 256) {
        int y = p / 28, xx = p % 28;
        float acc = 0.f;
#pragma unroll
        for (int u = 0; u < 7; u++)
#pragma unroll
            for (int v = 0; v < 7; v++)
                acc = fmaf(xt[(y + u) * 34 + xx + v], w[u * 7 + v], acc);
        float xv = xt[(y + 3) * 34 + xx + 3];
        sxg[p] = xv * (1.f / (1.f + expf(-acc)));
    }
    __syncthreads();
    float ts[10], tq[10];
#pragma unroll
    for (int o = 0; o < 10; o++) { ts[o] = 0.f; tq[o] = 0.f; }
    for (int r = 0; r < 4; r++) {
        for (int pp = tid; pp < 338; pp += 256) {
            int y = pp / 13, x0 = (pp % 13) * 2;
            float a0[10], a1[10];
#pragma unroll
            for (int o = 0; o < 10; o++) { a0[o] = 0.f; a1[o] = 0.f; }
#pragma unroll
            for (int u = 0; u < 3; u++)
#pragma unroll
                for (int v = 0; v < 3; v++) {
                    float xv0 = sxg[(y + u) * 28 + x0 + v];
                    float xv1 = sxg[(y + u) * 28 + x0 + v + 1];
                    const float* wp = &sw[((r * 3 + u) * 3 + v) * 10];
#pragma unroll
                    for (int o = 0; o < 10; o++) {
                        a0[o] = fmaf(xv0, wp[o], a0[o]);
                        a1[o] = fmaf(xv1, wp[o], a1[o]);
                    }
                }
#pragma unroll
            for (int o = 0; o < 10; o++) {
                size_t off = ((((size_t)b * 10 + o) * 4 + r) * 26 + y) * 26 + x0;
                g_buf0[off] = a0[o]; g_buf0[off + 1] = a1[o];
                ts[o] += a0[o] + a1[o];
                tq[o] += a0[o] * a0[o] + a1[o] * a1[o];
            }
        }
    }
#pragma unroll
    for (int o = 0; o < 10; o++) {
        float s = warpsum(ts[o]);
        float q = warpsum(tq[o]);
        if ((tid & 31) == 0) { atomicAdd(&bsum[o], s); atomicAdd(&bsq[o], q); }
    }
    __syncthreads();
    if (tid < 10) {
        atomicAdd(&g_sum[tid], (double)bsum[tid]);
        atomicAdd(&g_sq[tid], (double)bsq[tid]);
    }
}

// ---------------- layer-2 attention: fused BN0 pool + 7x7 GG conv, two-phase accs
__global__ void __launch_bounds__(256) attk2(const float* __restrict__ bng,
                                             const float* __restrict__ bnb, float invN) {
    constexpr int H = 26, H2 = 676, PWT = 34;
    extern __shared__ __align__(16) float dsm[];
    float* wd = dsm;                 // 3136 (duplicated weights, 4 rotations)
    float* pt = dsm + 3136;          // 2 * 8*34*34 = 18496
    __shared__ float sc[10], sh[10];
    int bb = blockIdx.x * 2, tid = threadIdx.x;
    bn_smem(tid, 0, bng, bnb, invN, sc, sh);
    for (int i = tid; i < 1568; i += 256) {
        float w = g_wa[i];
        wd[2 * i] = w; wd[2 * i + 1] = w;
    }
    for (int i = tid; i < 2 * 9248; i += 256) pt[i] = 0.f;
    __syncthreads();
    // fused pool: BN0+ReLU mean/max over channels, straight into padded tile
    for (int li = 0; li < 2; li++) {
        const float* inb = g_buf0 + (size_t)(bb + li) * 27040;
        for (int idx = tid; idx < 4 * H2; idx += 256) {
            int s = idx / H2, pos = idx - s * H2;
            int y = pos / H, x = pos - y * H;
            float sum = 0.f, mx = -3.4e38f;
#pragma unroll
            for (int c = 0; c < 10; c++) {
                float v = fmaf(inb[(c * 4 + s) * H2 + pos], sc[c], sh[c]);
                v = v > 0.f ? v : 0.f;
                sum += v; mx = fmaxf(mx, v);
            }
            pt[li * 9248 + (s * PWT + y + 3) * PWT + x + 3] = sum * 0.1f;
            pt[li * 9248 + ((4 + s) * PWT + y + 3) * PWT + x + 3] = mx;
        }
    }
    __syncthreads();
    // 208 tasks: li(2) x r(4) x y(26)
    if (tid < 208) {
        int li = tid / 104; int rem = tid - li * 104;
        int r = rem / 26, y = rem - r * 26;
        u64 acc[13];    // outputs (2i, 2i+1)
        u64 accB[14];   // outputs (2j-1, 2j)
#pragma unroll
        for (int i = 0; i < 13; i++) acc[i] = 0ull;
#pragma unroll
        for (int j = 0; j < 14; j++) accB[j] = 0ull;
        const float* base = pt + li * 9248;
        const u64* wr = (const u64*)&wd[r * 784];
        for (int js = 0; js < 8; js++) {
#pragma unroll
            for (int u = 0; u < 7; u++) {
                const u64* rp = (const u64*)&base[(js * PWT + y + u) * PWT];
                u64 P[16];
#pragma unroll
                for (int k = 0; k < 16; k++) P[k] = rp[k];
                const u64* wp = wr + (js * 49 + u * 7);
                u64 w0 = wp[0], w1 = wp[1], w2 = wp[2], w3 = wp[3];
                u64 w4 = wp[4], w5 = wp[5], w6 = wp[6];
#pragma unroll
                for (int i = 0; i < 13; i++) {
                    acc[i] = ffma2(P[i],     w0, acc[i]);
                    acc[i] = ffma2(P[i + 1], w2, acc[i]);
                    acc[i] = ffma2(P[i + 2], w4, acc[i]);
                    acc[i] = ffma2(P[i + 3], w6, acc[i]);
                }
#pragma unroll
                for (int j = 0; j < 14; j++) {
                    accB[j] = ffma2(P[j],     w1, accB[j]);
                    accB[j] = ffma2(P[j + 1], w3, accB[j]);
                    accB[j] = ffma2(P[j + 2], w5, accB[j]);
                }
            }
        }
        float* ob = &g_att[((size_t)(bb + li) * 4 + r) * H2 + y * H];
#pragma unroll
        for (int i = 0; i < 13; i++) {
            float al, ah; upk2(acc[i], al, ah);
            float b0l, b0h; upk2(accB[i], b0l, b0h);
            float b1l, b1h; upk2(accB[i + 1], b1l, b1h);
            float o0 = al + b0h, o1 = ah + b1l;
            ob[2 * i]     = 1.f / (1.f + expf(-o0));
            ob[2 * i + 1] = 1.f / (1.f + expf(-o1));
        }
    }
}

// ---------------- layer-2 GG conv, y-split x3, BN0 inline, stats1 ----------------
__global__ void __launch_bounds__(192, 2) convL2(const float* __restrict__ in,
                                                 float* __restrict__ out,
                                                 const float* __restrict__ bng,
                                                 const float* __restrict__ bnb, float invN) {
    extern __shared__ float sm[];
    float* sx = sm;            // 40*10*28 = 11200 (+8 pad)
    float* sw = sm + 11208;    // 14400
    __shared__ float bsum[10], bsq[10], sc[10], sh[10];
    int b = blockIdx.x / 3, yt = blockIdx.x % 3, y0 = yt * 8;
    int tid = threadIdx.x;
    if (tid < 10) { bsum[tid] = 0.f; bsq[tid] = 0.f; }
    bn_smem(tid, 0, bng, bnb, invN, sc, sh);
    if (tid < 8) sx[11200 + tid] = 0.f;
    __syncthreads();
    const float* inb = in + (size_t)b * 27040;
    const float* attp = g_att + (size_t)b * 2704;
    for (int idx = tid; idx < 40 * 10 * 26; idx += 192) {
        int x = idx % 26; int t = idx / 26; int yy = t % 10; int is = t / 10;
        int gy = y0 + yy;
        float v = inb[is * 676 + gy * 26 + x];
        v = fmaf(v, sc[is >> 2], sh[is >> 2]);
        v = v > 0.f ? v : 0.f;
        v *= __ldg(&attp[(is & 3) * 676 + gy * 26 + x]);
        sx[(is * 10 + yy) * 28 + x] = v;
    }
    {
        const float4* wg = (const float4*)g_wc;
        float4* swv = (float4*)sw;
        for (int i = tid; i < 3600; i += 192) swv[i] = wg[i];
    }
    __syncthreads();

    float ts[10], tq[10];
#pragma unroll
    for (int o = 0; o < 10; o++) { ts[o] = 0.f; tq[o] = 0.f; }

    {
        int task = tid;
        int q = task % 6;
        int yy = (task / 6) % 8;
        int r = task / 48;
        int x0 = q * 4;
        u64 acc[4][5];
#pragma unroll
        for (int p = 0; p < 4; p++)
#pragma unroll
            for (int k = 0; k < 5; k++) acc[p][k] = 0ull;
        const float* wr = &sw[r * 3600];
        const float* xb0 = &sx[yy * 28 + x0];
        for (int is = 0; is < 40; is++) {
            const float* xb = xb0 + is * 280;
            const float* wb = wr + is * 90;
#pragma unroll
            for (int u = 0; u < 3; u++) {
                float4 v4 = *(const float4*)(xb + u * 28);
                float2 v2 = *(const float2*)(xb + u * 28 + 4);
                u64 xd[6];
                xd[0] = pk2(v4.x, v4.x); xd[1] = pk2(v4.y, v4.y);
                xd[2] = pk2(v4.z, v4.z); xd[3] = pk2(v4.w, v4.w);
                xd[4] = pk2(v2.x, v2.x); xd[5] = pk2(v2.y, v2.y);
#pragma unroll
                for (int v = 0; v < 3; v++) {
                    const u64* wp = (const u64*)(wb + u * 30 + v * 10);
#pragma unroll
                    for (int k = 0; k < 5; k++) {
                        u64 w2 = wp[k];
#pragma unroll
                        for (int p = 0; p < 4; p++)
                            acc[p][k] = ffma2(xd[v + p], w2, acc[p][k]);
                    }
                }
            }
        }
        int y = y0 + yy;
#pragma unroll
        for (int p = 0; p < 4; p++) {
            int x = x0 + p;
#pragma unroll
            for (int k = 0; k < 5; k++) {
                float lo, hi; upk2(acc[p][k], lo, hi);
                ts[2 * k] += lo;     tq[2 * k] += lo * lo;
                ts[2 * k + 1] += hi; tq[2 * k + 1] += hi * hi;
                size_t o0 = ((((size_t)b * 10 + 2 * k) * 4 + r) * 24 + y) * 24 + x;
                out[o0] = lo;
                out[o0 + (size_t)2304] = hi;
            }
        }
    }
#pragma unroll
    for (int o = 0; o < 10; o++) {
        float s = warpsum(ts[o]);
        float qv = warpsum(tq[o]);
        if ((tid & 31) == 0) { atomicAdd(&bsum[o], s); atomicAdd(&bsq[o], qv); }
    }
    __syncthreads();
    if (tid < 10) {
        atomicAdd(&g_sum[10 + tid], (double)bsum[tid]);
        atomicAdd(&g_sq[10 + tid], (double)bsq[tid]);
    }
}

// ---------------- fused layer ----------------
template <int H, int NT, int PXCH, int GIMG, bool LPOOL>
__global__ void __launch_bounds__(NT, 2) fusedgg(const float* __restrict__ in,
                                                 float* __restrict__ out,
                                                 int wlayer, int alayer, int statsIdx,
                                                 int bnIdx, const float* __restrict__ bng,
                                                 const float* __restrict__ bnb, float invN) {
    constexpr int HO = H - 2, WO = H - 2, HP = (H + 3) & ~3;
    constexpr int H2 = H * H, PLANE = H * HP;
    constexpr int NQ = (WO + PXCH - 1) / PXCH;
    constexpr int TASKS = GIMG * 4 * HO * NQ;
    constexpr int PW4R = ((H + 6) + 3) & ~3;
    constexpr int PW4 = (PW4R % 16 == 0) ? PW4R + 4 : PW4R;
    constexpr int TILE = 8 * PW4 * PW4;
    constexpr int NQA = (H + 3) / 4;
    extern __shared__ float sm[];
    float* sx = sm;
    float* sw = sm + GIMG * 40 * PLANE + 8;
    float* tile = sw;
    float* wa_s = sw + TILE + 16;
    float* att_s = wa_s + 1568;
    __shared__ float bsum[10], bsq[10], sc[10], sh[10];
    int grp = blockIdx.x, tid = threadIdx.x;
    if (tid < 10) { bsum[tid] = 0.f; bsq[tid] = 0.f; }
    bn_smem(tid, bnIdx, bng, bnb, invN, sc, sh);
    if (tid < 8) sx[GIMG * 40 * PLANE + tid] = 0.f;
    __syncthreads();

    for (int li = 0; li < GIMG; li++) {
        int b = grp * GIMG + li;
        if (LPOOL) {
            const float* inb = in + (size_t)b * 40 * 576;
            for (int idx = tid; idx < 40 * H2; idx += NT) {
                int is = idx / H2, pos = idx - is * H2;
                int y = pos / H, x = pos - y * H;
                const float* p = inb + (size_t)is * 576 + (2 * y) * 24 + 2 * x;
                float2 A = *(const float2*)p;
                float2 Bv = *(const float2*)(p + 24);
                float s = sc[is >> 2], t = sh[is >> 2];
                float v0 = fmaf(A.x, s, t), v1 = fmaf(A.y, s, t);
                float v2 = fmaf(Bv.x, s, t), v3 = fmaf(Bv.y, s, t);
                float v = fmaxf(fmaxf(v0, v1), fmaxf(v2, v3));
                v = v > 0.f ? v : 0.f;
                sx[((li * 40 + is) * H + y) * HP + x] = v;
            }
        } else {
            const float* inb = in + (size_t)b * 40 * H2;
            for (int idx = tid; idx < 40 * H2; idx += NT) {
                int is = idx / H2, pos = idx - is * H2;
                int y = pos / H, x = pos - y * H;
                float v = inb[idx];
                v = fmaf(v, sc[is >> 2], sh[is >> 2]);
                v = v > 0.f ? v : 0.f;
                sx[((li * 40 + is) * H + y) * HP + x] = v;
            }
        }
    }
    for (int i = tid; i < 1568; i += NT) wa_s[i] = g_wa[alayer * 1568 + i];
    __syncthreads();

    for (int li = 0; li < GIMG; li++) {
        for (int i = tid; i < TILE; i += NT) tile[i] = 0.f;
        __syncthreads();
        for (int idx = tid; idx < 4 * H2; idx += NT) {
            int s = idx / H2, pos = idx - s * H2;
            int y = pos / H, x = pos - y * H;
            float sum = 0.f, mx = -3.4e38f;
#pragma unroll
            for (int c = 0; c < 10; c++) {
                float v = sx[((li * 40 + c * 4 + s) * H + y) * HP + x];
                sum += v; mx = fmaxf(mx, v);
            }
            tile[(s * PW4 + y + 3) * PW4 + x + 3] = sum * 0.1f;
            tile[((4 + s) * PW4 + y + 3) * PW4 + x + 3] = mx;
        }
        __syncthreads();
        for (int t = tid; t < 4 * NQA * H; t += NT) {
            int q = t % NQA; int y = (t / NQA) % H; int r = t / (NQA * H);
            int x0 = q * 4;
            float a0 = 0.f, a1 = 0.f, a2 = 0.f, a3 = 0.f;
            const float* wb0 = &wa_s[r * 392];
#pragma unroll
            for (int js = 0; js < 8; js++) {
#pragma unroll
                for (int u = 0; u < 7; u++) {
                    const float* rowp = &tile[(js * PW4 + y + u) * PW4 + x0];
                    float4 A = *(const float4*)rowp;
                    float4 Bv = *(const float4*)(rowp + 4);
                    float2 Cv = *(const float2*)(rowp + 8);
                    float rr[10] = {A.x, A.y, A.z, A.w, Bv.x, Bv.y, Bv.z, Bv.w, Cv.x, Cv.y};
                    const float* wb = &wb0[js * 49 + u * 7];
#pragma unroll
                    for (int v = 0; v < 7; v++) {
                        float w = wb[v];
                        a0 = fmaf(rr[v], w, a0);
                        a1 = fmaf(rr[v + 1], w, a1);
                        a2 = fmaf(rr[v + 2], w, a2);
                        a3 = fmaf(rr[v + 3], w, a3);
                    }
                }
            }
            float* ob = &att_s[(li * 4 + r) * H2 + y * H];
            if (x0 < H)     ob[x0]     = 1.f / (1.f + expf(-a0));
            if (x0 + 1 < H) ob[x0 + 1] = 1.f / (1.f + expf(-a1));
            if (x0 + 2 < H) ob[x0 + 2] = 1.f / (1.f + expf(-a2));
            if (x0 + 3 < H) ob[x0 + 3] = 1.f / (1.f + expf(-a3));
        }
        __syncthreads();
    }

    for (int li = 0; li < GIMG; li++)
        for (int idx = tid; idx < 40 * H2; idx += NT) {
            int is = idx / H2, pos = idx - is * H2;
            int y = pos / H, x = pos - y * H;
            sx[((li * 40 + is) * H + y) * HP + x] *= att_s[(li * 4 + (is & 3)) * H2 + pos];
        }
    __syncthreads();
    {
        const float4* wg = (const float4*)&g_wc[wlayer * 14400];
        float4* swv = (float4*)sw;
        for (int i = tid; i < 3600; i += NT) swv[i] = wg[i];
    }
    __syncthreads();

    float ts[10], tq[10];
#pragma unroll
    for (int o = 0; o < 10; o++) { ts[o] = 0.f; tq[o] = 0.f; }

    for (int task = tid; task < TASKS; task += NT) {
        int q = task % NQ;
        int t2 = task / NQ;
        int y = t2 % HO; t2 /= HO;
        int r = t2 & 3; int li = t2 >> 2;
        int x0 = q * PXCH;
        u64 acc[PXCH][5];
#pragma unroll
        for (int p = 0; p < PXCH; p++)
#pragma unroll
            for (int k = 0; k < 5; k++) acc[p][k] = 0ull;
        const float* wr = &sw[r * 3600];
        const float* xb0 = &sx[(li * 40 * H + y) * HP + x0];
        for (int is = 0; is < 40; is++) {
            const float* xb = xb0 + is * PLANE;
            const float* wb = wr + is * 90;
#pragma unroll
            for (int u = 0; u < 3; u++) {
                u64 xd[PXCH + 2];
                if (PXCH == 4) {
                    float4 v4 = *(const float4*)(xb + u * HP);
                    float2 v2 = *(const float2*)(xb + u * HP + 4);
                    xd[0] = pk2(v4.x, v4.x); xd[1] = pk2(v4.y, v4.y);
                    xd[2] = pk2(v4.z, v4.z); xd[3] = pk2(v4.w, v4.w);
                    xd[4] = pk2(v2.x, v2.x); xd[5] = pk2(v2.y, v2.y);
                } else {
                    float2 vA = *(const float2*)(xb + u * HP);
                    float2 vB = *(const float2*)(xb + u * HP + 2);
                    xd[0] = pk2(vA.x, vA.x); xd[1] = pk2(vA.y, vA.y);
                    xd[2] = pk2(vB.x, vB.x); xd[3] = pk2(vB.y, vB.y);
                }
#pragma unroll
                for (int v = 0; v < 3; v++) {
                    const u64* wp = (const u64*)(wb + u * 30 + v * 10);
#pragma unroll
                    for (int k = 0; k < 5; k++) {
                        u64 w2 = wp[k];
#pragma unroll
                        for (int p = 0; p < PXCH; p++)
                            acc[p][k] = ffma2(xd[v + p], w2, acc[p][k]);
                    }
                }
            }
        }
        int b = grp * GIMG + li;
#pragma unroll
        for (int p = 0; p < PXCH; p++) {
            int x = x0 + p;
            if (x < WO) {
#pragma unroll
                for (int k = 0; k < 5; k++) {
                    float lo, hi; upk2(acc[p][k], lo, hi);
                    ts[2 * k] += lo;     tq[2 * k] += lo * lo;
                    ts[2 * k + 1] += hi; tq[2 * k + 1] += hi * hi;
                    size_t o0 = ((((size_t)b * 10 + 2 * k) * 4 + r) * HO + y) * WO + x;
                    out[o0] = lo;
                    out[o0 + (size_t)4 * HO * WO] = hi;
                }
            }
        }
    }
#pragma unroll
    for (int o = 0; o < 10; o++) {
        float s = warpsum(ts[o]);
        float qv = warpsum(tq[o]);
        if ((tid & 31) == 0) { atomicAdd(&bsum[o], s); atomicAdd(&bsq[o], qv); }
    }
    __syncthreads();
    if (tid < 10) {
        atomicAdd(&g_sum[statsIdx * 10 + tid], (double)bsum[tid]);
        atomicAdd(&g_sq[statsIdx * 10 + tid], (double)bsq[tid]);
    }
}

// ---------------- layer 7 fused ----------------
__global__ void __launch_bounds__(64) conv7k(const float* __restrict__ in,
                                             float* __restrict__ outp,
                                             const float* __restrict__ bng,
                                             const float* __restrict__ bnb, float invN) {
    __shared__ float sx[640], yv[40], sc[10], sh[10];
    __shared__ float tile[8 * 12 * 12 + 16];
    __shared__ float wa_s[1568];
    __shared__ float att_s[64];
    int b = blockIdx.x, tid = threadIdx.x;
    bn_smem(tid, 5, bng, bnb, invN, sc, sh);
    for (int i = tid; i < 8 * 144 + 16; i += 64) tile[i] = 0.f;
    for (int i = tid; i < 1568; i += 64) wa_s[i] = g_wa[5 * 1568 + i];
    __syncthreads();
    for (int idx = tid; idx < 640; idx += 64) {
        int c = idx >> 6;
        float v = in[(size_t)b * 640 + idx];
        v = fmaf(v, sc[c], sh[c]);
        sx[idx] = v > 0.f ? v : 0.f;
    }
    __syncthreads();
    if (tid < 64) {
        int s = tid / 16, pos = tid & 15;
        int y = pos >> 2, x = pos & 3;
        float sum = 0.f, mx = -3.4e38f;
#pragma unroll
        for (int c = 0; c < 10; c++) {
            float v = sx[(c * 4 + s) * 16 + pos];
            sum += v; mx = fmaxf(mx, v);
        }
        tile[(s * 12 + y + 3) * 12 + x + 3] = sum * 0.1f;
        tile[((4 + s) * 12 + y + 3) * 12 + x + 3] = mx;
    }
    __syncthreads();
    if (tid < 64) {
        int r = tid / 16, pos = tid & 15;
        int y = pos >> 2, x = pos & 3;
        float acc = 0.f;
        const float* wb0 = &wa_s[r * 392];
#pragma unroll
        for (int js = 0; js < 8; js++)
#pragma unroll
            for (int u = 0; u < 7; u++) {
                const float* rowp = &tile[(js * 12 + y + u) * 12 + x];
                const float* wb = &wb0[js * 49 + u * 7];
#pragma unroll
                for (int v = 0; v < 7; v++) acc = fmaf(rowp[v], wb[v], acc);
            }
        att_s[r * 16 + pos] = 1.f / (1.f + expf(-acc));
    }
    __syncthreads();
    for (int idx = tid; idx < 640; idx += 64) {
        int is = (idx >> 4) & 3;
        sx[idx] *= att_s[is * 16 + (idx & 15)];
    }
    __syncthreads();
    if (tid < 40) {
        int r = tid / 10, o = tid % 10;
        float acc = 0.f;
        for (int is = 0; is < 40; is++) {
#pragma unroll
            for (int t = 0; t < 16; t++)
                acc = fmaf(sx[is * 16 + t], __ldg(&g_wc7[((r * 40 + is) * 16 + t) * 10 + o]), acc);
        }
        yv[r * 10 + o] = acc;
    }
    __syncthreads();
    if (tid < 10) {
        float m = yv[tid];
        for (int r = 1; r < 4; r++) m = fmaxf(m, yv[r * 10 + tid]);
        outp[(size_t)b * 10 + tid] = m;
    }
}

// ---------------- launch ----------------
extern "C" void kernel_launch(void* const* d_in, const int* in_sizes, int n_in,
                              void* d_out, int out_size) {
    const float* x  = (const float*)d_in[0];
    const float* c1 = (const float*)d_in[1];
    const float* a1 = (const float*)d_in[2];
    const float* c2 = (const float*)d_in[3];
    const float* a2 = (const float*)d_in[4];
    const float* c3 = (const float*)d_in[5];
    const float* a3 = (const float*)d_in[6];
    const float* c4 = (const float*)d_in[7];
    const float* a4 = (const float*)d_in[8];
    const float* c5 = (const float*)d_in[9];
    const float* a5 = (const float*)d_in[10];
    const float* c6 = (const float*)d_in[11];
    const float* a6 = (const float*)d_in[12];
    const float* c7 = (const float*)d_in[13];
    const float* a7 = (const float*)d_in[14];
    const float* bn_g[6] = {(const float*)d_in[15], (const float*)d_in[17], (const float*)d_in[19],
                            (const float*)d_in[21], (const float*)d_in[23], (const float*)d_in[25]};
    const float* bn_b[6] = {(const float*)d_in[16], (const float*)d_in[18], (const float*)d_in[20],
                            (const float*)d_in[22], (const float*)d_in[24], (const float*)d_in[26]};
    float* out = (float*)d_out;

    int B = in_sizes[0] / 784;
    if (B > BMAX) B = BMAX;

    float *b0, *b1;
    cudaGetSymbolAddress((void**)&b0, g_buf0);
    cudaGetSymbolAddress((void**)&b1, g_buf1);

    const int SMA2 = (3136 + 2 * 9248) * 4;
    const int SML2 = (11208 + 14400) * 4;
    const int SM3 = (2 * 40 * 12 * 12 + 8 + 14400) * 4;
    const int SM4 = (2 * 40 * 10 * 12 + 8 + 14400) * 4;
    const int SM5 = (4 * 40 * 8 * 8 + 8 + 14400) * 4;
    const int SM6 = (4 * 40 * 6 * 8 + 8 + 14400) * 4;
    cudaFuncSetAttribute((const void*)attk2,  cudaFuncAttributeMaxDynamicSharedMemorySize, SMA2);
    cudaFuncSetAttribute((const void*)convL2, cudaFuncAttributeMaxDynamicSharedMemorySize, SML2);
    cudaFuncSetAttribute((const void*)fusedgg<12, 256, 4, 2, true>,  cudaFuncAttributeMaxDynamicSharedMemorySize, SM3);
    cudaFuncSetAttribute((const void*)fusedgg<10, 256, 2, 2, false>, cudaFuncAttributeMaxDynamicSharedMemorySize, SM4);
    cudaFuncSetAttribute((const void*)fusedgg<8, 288, 2, 4, false>,  cudaFuncAttributeMaxDynamicSharedMemorySize, SM5);
    cudaFuncSetAttribute((const void*)fusedgg<6, 128, 2, 4, false>,  cudaFuncAttributeMaxDynamicSharedMemorySize, SM6);

    prepk<<<64, 128>>>(c1, c2, c3, c4, c5, c6, c7, a1, a2, a3, a4, a5, a6, a7);

    l1k<<<B, 256>>>(x);

    float invN0 = 1.f / (float)(B * 4 * 676);
    attk2<<<B / 2, 256, SMA2>>>(bn_g[0], bn_b[0], invN0);
    convL2<<<B * 3, 192, SML2>>>(b0, b1, bn_g[0], bn_b[0], invN0);

    fusedgg<12, 256, 4, 2, true><<<B / 2, 256, SM3>>>(b1, b0, 1, 1, 2, 1, bn_g[1], bn_b[1], 1.f / (float)(B * 4 * 576));
    fusedgg<10, 256, 2, 2, false><<<B / 2, 256, SM4>>>(b0, b1, 2, 2, 3, 2, bn_g[2], bn_b[2], 1.f / (float)(B * 4 * 100));
    fusedgg<8, 288, 2, 4, false><<<B / 4, 288, SM5>>>(b1, b0, 3, 3, 4, 3, bn_g[3], bn_b[3], 1.f / (float)(B * 4 * 64));
    fusedgg<6, 128, 2, 4, false><<<B / 4, 128, SM6>>>(b0, b1, 4, 4, 5, 4, bn_g[4], bn_b[4], 1.f / (float)(B * 4 * 36));
    conv7k<<<B, 64>>>(b1, out, bn_g[5], bn_b[5], 1.f / (float)(B * 4 * 16));
}

// round 15
// speedup vs baseline: 1.1624x; 1.0861x over previous
#include <cuda_runtime.h>
#include <cstdint>
#include <math.h>

#define BMAX 2048
__device__ float g_buf0[BMAX * 10 * 4 * 26 * 26];
__device__ float g_buf1[BMAX * 10 * 4 * 24 * 24];
__device__ float g_att [BMAX * 4 * 26 * 26];

__device__ double g_sum[60], g_sq[60];

__device__ float g_wl[4 * 3 * 3 * 10];
__device__ __align__(16) float g_wc[5 * 4 * 10 * 4 * 3 * 3 * 10];
__device__ float g_wc7[4 * 10 * 4 * 4 * 4 * 10];
__device__ float g_wa1[49];
__device__ float g_wa[6 * 4 * 2 * 4 * 7 * 7];

typedef unsigned long long u64;

__device__ __forceinline__ u64 pk2(float lo, float hi) {
    u64 r; asm("mov.b64 %0,{%1,%2};" : "=l"(r) : "f"(lo), "f"(hi)); return r;
}
__device__ __forceinline__ void upk2(u64 v, float& lo, float& hi) {
    asm("mov.b64 {%0,%1},%2;" : "=f"(lo), "=f"(hi) : "l"(v));
}
__device__ __forceinline__ u64 ffma2(u64 a, u64 b, u64 c) {
    u64 d; asm("fma.rn.f32x2 %0,%1,%2,%3;" : "=l"(d) : "l"(a), "l"(b), "l"(c)); return d;
}

__device__ __forceinline__ void rotmap(int r, int u, int v, int K, int& su, int& sv) {
    switch (r & 3) {
        case 0: su = u;         sv = v;         break;
        case 1: su = v;         sv = K - 1 - u; break;
        case 2: su = K - 1 - u; sv = K - 1 - v; break;
        default: su = K - 1 - v; sv = u;        break;
    }
}

__device__ __forceinline__ float warpsum(float v) {
    for (int o = 16; o > 0; o >>= 1) v += __shfl_down_sync(0xffffffffu, v, o);
    return v;
}

__device__ __forceinline__ void bn_smem(int tid, int bnIdx, const float* bng,
                                        const float* bnb, float invN,
                                        float* sc, float* sh) {
    if (tid < 10) {
        if (bnIdx >= 0) {
            double m = g_sum[bnIdx * 10 + tid] * (double)invN;
            double var = g_sq[bnIdx * 10 + tid] * (double)invN - m * m;
            float rstd = rsqrtf((float)var + 2e-5f);
            float s = bng[tid] * rstd;
            sc[tid] = s; sh[tid] = bnb[tid] - (float)m * s;
        } else { sc[tid] = 1.f; sh[tid] = 0.f; }
    }
}

// ---------------- prep ----------------
__global__ void prepk(const float* c1, const float* c2, const float* c3, const float* c4,
                      const float* c5, const float* c6, const float* c7,
                      const float* a1, const float* a2, const float* a3, const float* a4,
                      const float* a5, const float* a6, const float* a7) {
    int tid = blockIdx.x * blockDim.x + threadIdx.x;
    int nth = gridDim.x * blockDim.x;
    const float* cws[5] = {c2, c3, c4, c5, c6};
    const float* aws[6] = {a2, a3, a4, a5, a6, a7};

    for (int idx = tid; idx < 360; idx += nth) {
        int o = idx % 10, t = idx / 10;
        int v = t % 3; t /= 3; int u = t % 3; int r = t / 3;
        int su, sv; rotmap(r, u, v, 3, su, sv);
        g_wl[idx] = c1[o * 9 + su * 3 + sv];
    }
    for (int idx = tid; idx < 5 * 14400; idx += nth) {
        int o = idx % 10; int t = idx / 10;
        int v = t % 3; t /= 3; int u = t % 3; t /= 3;
        int s = t & 3; t >>= 2; int i = t % 10; t /= 10;
        int r = t & 3; int l = t >> 2;
        int sp = (s - r) & 3; int su, sv; rotmap(r, u, v, 3, su, sv);
        g_wc[idx] = cws[l][((o * 10 + i) * 4 + sp) * 9 + su * 3 + sv];
    }
    for (int idx = tid; idx < 25600; idx += nth) {
        int o = idx % 10; int t = idx / 10;
        int v = t & 3; t >>= 2; int u = t & 3; t >>= 2;
        int s = t & 3; t >>= 2; int i = t % 10; int r = t / 10;
        int sp = (s - r) & 3; int su, sv; rotmap(r, u, v, 4, su, sv);
        g_wc7[idx] = c7[((o * 10 + i) * 4 + sp) * 16 + su * 4 + sv];
    }
    for (int idx = tid; idx < 49; idx += nth) g_wa1[idx] = a1[idx] + a1[49 + idx];
    for (int idx = tid; idx < 6 * 1568; idx += nth) {
        int v = idx % 7; int t = idx / 7;
        int u = t % 7; t /= 7; int s = t & 3; t >>= 2;
        int i = t & 1; t >>= 1; int r = t & 3; int l = t >> 2;
        int sp = (s - r) & 3; int su, sv; rotmap(r, u, v, 7, su, sv);
        g_wa[idx] = aws[l][(i * 4 + sp) * 49 + su * 7 + sv];
    }
    for (int idx = tid; idx < 60; idx += nth) { g_sum[idx] = 0.0; g_sq[idx] = 0.0; }
}

// ---------------- layer 1: attention + gate + lifting conv + stats0 ----------------
__global__ void __launch_bounds__(256) l1k(const float* __restrict__ x) {
    __shared__ float xt[34 * 34];
    __shared__ float sxg[784];
    __shared__ float w[49];
    __shared__ float sw[360];
    __shared__ float bsum[10], bsq[10];
    int b = blockIdx.x, tid = threadIdx.x;
    for (int i = tid; i < 34 * 34; i += 256) xt[i] = 0.f;
    for (int i = tid; i < 49; i += 256) w[i] = g_wa1[i];
    for (int i = tid; i < 360; i += 256) sw[i] = g_wl[i];
    if (tid < 10) { bsum[tid] = 0.f; bsq[tid] = 0.f; }
    __syncthreads();
    for (int i = tid; i < 784; i += 256) {
        int y = i / 28, xx = i % 28;
        xt[(y + 3) * 34 + xx + 3] = x[(size_t)b * 784 + i];
    }
    __syncthreads();
    for (int p = tid; p < 784; p += 256) {
        int y = p / 28, xx = p % 28;
        float acc = 0.f;
#pragma unroll
        for (int u = 0; u < 7; u++)
#pragma unroll
            for (int v = 0; v < 7; v++)
                acc = fmaf(xt[(y + u) * 34 + xx + v], w[u * 7 + v], acc);
        float xv = xt[(y + 3) * 34 + xx + 3];
        sxg[p] = xv * (1.f / (1.f + expf(-acc)));
    }
    __syncthreads();
    float ts[10], tq[10];
#pragma unroll
    for (int o = 0; o < 10; o++) { ts[o] = 0.f; tq[o] = 0.f; }
    for (int r = 0; r < 4; r++) {
        for (int pp = tid; pp < 338; pp += 256) {
            int y = pp / 13, x0 = (pp % 13) * 2;
            float a0[10], a1[10];
#pragma unroll
            for (int o = 0; o < 10; o++) { a0[o] = 0.f; a1[o] = 0.f; }
#pragma unroll
            for (int u = 0; u < 3; u++)
#pragma unroll
                for (int v = 0; v < 3; v++) {
                    float xv0 = sxg[(y + u) * 28 + x0 + v];
                    float xv1 = sxg[(y + u) * 28 + x0 + v + 1];
                    const float* wp = &sw[((r * 3 + u) * 3 + v) * 10];
#pragma unroll
                    for (int o = 0; o < 10; o++) {
                        a0[o] = fmaf(xv0, wp[o], a0[o]);
                        a1[o] = fmaf(xv1, wp[o], a1[o]);
                    }
                }
#pragma unroll
            for (int o = 0; o < 10; o++) {
                size_t off = ((((size_t)b * 10 + o) * 4 + r) * 26 + y) * 26 + x0;
                g_buf0[off] = a0[o]; g_buf0[off + 1] = a1[o];
                ts[o] += a0[o] + a1[o];
                tq[o] += a0[o] * a0[o] + a1[o] * a1[o];
            }
        }
    }
#pragma unroll
    for (int o = 0; o < 10; o++) {
        float s = warpsum(ts[o]);
        float q = warpsum(tq[o]);
        if ((tid & 31) == 0) { atomicAdd(&bsum[o], s); atomicAdd(&bsq[o], q); }
    }
    __syncthreads();
    if (tid < 10) {
        atomicAdd(&g_sum[tid], (double)bsum[tid]);
        atomicAdd(&g_sq[tid], (double)bsq[tid]);
    }
}

// ---------------- layer-2 attention: fused BN0 pool + 7x7 GG conv, two-phase accs
__global__ void __launch_bounds__(256) attk2(const float* __restrict__ bng,
                                             const float* __restrict__ bnb, float invN) {
    constexpr int H = 26, H2 = 676, PWT = 34;
    extern __shared__ __align__(16) float dsm[];
    float* wd = dsm;                 // 3136 (duplicated weights, 4 rotations)
    float* pt = dsm + 3136;          // 2 * 8*34*34 = 18496
    __shared__ float sc[10], sh[10];
    int bb = blockIdx.x * 2, tid = threadIdx.x;
    bn_smem(tid, 0, bng, bnb, invN, sc, sh);
    for (int i = tid; i < 1568; i += 256) {
        float w = g_wa[i];
        wd[2 * i] = w; wd[2 * i + 1] = w;
    }
    for (int i = tid; i < 2 * 9248; i += 256) pt[i] = 0.f;
    __syncthreads();
    for (int li = 0; li < 2; li++) {
        const float* inb = g_buf0 + (size_t)(bb + li) * 27040;
        for (int idx = tid; idx < 4 * H2; idx += 256) {
            int s = idx / H2, pos = idx - s * H2;
            int y = pos / H, x = pos - y * H;
            float sum = 0.f, mx = -3.4e38f;
#pragma unroll
            for (int c = 0; c < 10; c++) {
                float v = fmaf(inb[(c * 4 + s) * H2 + pos], sc[c], sh[c]);
                v = v > 0.f ? v : 0.f;
                sum += v; mx = fmaxf(mx, v);
            }
            pt[li * 9248 + (s * PWT + y + 3) * PWT + x + 3] = sum * 0.1f;
            pt[li * 9248 + ((4 + s) * PWT + y + 3) * PWT + x + 3] = mx;
        }
    }
    __syncthreads();
    if (tid < 208) {
        int li = tid / 104; int rem = tid - li * 104;
        int r = rem / 26, y = rem - r * 26;
        u64 acc[13];
        u64 accB[14];
#pragma unroll
        for (int i = 0; i < 13; i++) acc[i] = 0ull;
#pragma unroll
        for (int j = 0; j < 14; j++) accB[j] = 0ull;
        const float* base = pt + li * 9248;
        const u64* wr = (const u64*)&wd[r * 784];
        for (int js = 0; js < 8; js++) {
#pragma unroll
            for (int u = 0; u < 7; u++) {
                const u64* rp = (const u64*)&base[(js * PWT + y + u) * PWT];
                u64 P[16];
#pragma unroll
                for (int k = 0; k < 16; k++) P[k] = rp[k];
                const u64* wp = wr + (js * 49 + u * 7);
                u64 w0 = wp[0], w1 = wp[1], w2 = wp[2], w3 = wp[3];
                u64 w4 = wp[4], w5 = wp[5], w6 = wp[6];
#pragma unroll
                for (int i = 0; i < 13; i++) {
                    acc[i] = ffma2(P[i],     w0, acc[i]);
                    acc[i] = ffma2(P[i + 1], w2, acc[i]);
                    acc[i] = ffma2(P[i + 2], w4, acc[i]);
                    acc[i] = ffma2(P[i + 3], w6, acc[i]);
                }
#pragma unroll
                for (int j = 0; j < 14; j++) {
                    accB[j] = ffma2(P[j],     w1, accB[j]);
                    accB[j] = ffma2(P[j + 1], w3, accB[j]);
                    accB[j] = ffma2(P[j + 2], w5, accB[j]);
                }
            }
        }
        float* ob = &g_att[((size_t)(bb + li) * 4 + r) * H2 + y * H];
#pragma unroll
        for (int i = 0; i < 13; i++) {
            float al, ah; upk2(acc[i], al, ah);
            float b0l, b0h; upk2(accB[i], b0l, b0h);
            float b1l, b1h; upk2(accB[i + 1], b1l, b1h);
            float o0 = al + b0h, o1 = ah + b1l;
            ob[2 * i]     = 1.f / (1.f + expf(-o0));
            ob[2 * i + 1] = 1.f / (1.f + expf(-o1));
        }
    }
}

// ---------------- layer-2 GG conv: 384 threads, PXCH=2, 24 warps/SM ----------------
__global__ void __launch_bounds__(384, 2) convL2(const float* __restrict__ in,
                                                 float* __restrict__ out,
                                                 const float* __restrict__ bng,
                                                 const float* __restrict__ bnb, float invN) {
    extern __shared__ float sm[];
    float* sx = sm;            // 40*10*28 = 11200 (+8 pad)
    float* sw = sm + 11208;    // 14400
    __shared__ float bsum[10], bsq[10], sc[10], sh[10];
    int b = blockIdx.x / 3, yt = blockIdx.x % 3, y0 = yt * 8;
    int tid = threadIdx.x;
    if (tid < 10) { bsum[tid] = 0.f; bsq[tid] = 0.f; }
    bn_smem(tid, 0, bng, bnb, invN, sc, sh);
    if (tid < 8) sx[11200 + tid] = 0.f;
    __syncthreads();
    const float* inb = in + (size_t)b * 27040;
    const float* attp = g_att + (size_t)b * 2704;
    for (int idx = tid; idx < 40 * 10 * 26; idx += 384) {
        int x = idx % 26; int t = idx / 26; int yy = t % 10; int is = t / 10;
        int gy = y0 + yy;
        float v = inb[is * 676 + gy * 26 + x];
        v = fmaf(v, sc[is >> 2], sh[is >> 2]);
        v = v > 0.f ? v : 0.f;
        v *= __ldg(&attp[(is & 3) * 676 + gy * 26 + x]);
        sx[(is * 10 + yy) * 28 + x] = v;
    }
    {
        const float4* wg = (const float4*)g_wc;
        float4* swv = (float4*)sw;
        for (int i = tid; i < 3600; i += 384) swv[i] = wg[i];
    }
    __syncthreads();

    float ts[10], tq[10];
#pragma unroll
    for (int o = 0; o < 10; o++) { ts[o] = 0.f; tq[o] = 0.f; }

    {
        // 384 tasks: q(12) x yy(8) x r(4); r uniform per warp (96 = 3 warps)
        int task = tid;
        int q = task % 12;
        int yy = (task / 12) % 8;
        int r = task / 96;
        int x0 = q * 2;
        u64 acc[2][5];
#pragma unroll
        for (int p = 0; p < 2; p++)
#pragma unroll
            for (int k = 0; k < 5; k++) acc[p][k] = 0ull;
        const float* wr = &sw[r * 3600];
        const float* xb0 = &sx[yy * 28 + x0];
        for (int is = 0; is < 40; is++) {
            const float* xb = xb0 + is * 280;
            const float* wb = wr + is * 90;
#pragma unroll
            for (int u = 0; u < 3; u++) {
                float2 vA = *(const float2*)(xb + u * 28);
                float2 vB = *(const float2*)(xb + u * 28 + 2);
                u64 xd[4];
                xd[0] = pk2(vA.x, vA.x); xd[1] = pk2(vA.y, vA.y);
                xd[2] = pk2(vB.x, vB.x); xd[3] = pk2(vB.y, vB.y);
#pragma unroll
                for (int v = 0; v < 3; v++) {
                    const u64* wp = (const u64*)(wb + u * 30 + v * 10);
#pragma unroll
                    for (int k = 0; k < 5; k++) {
                        u64 w2 = wp[k];
                        acc[0][k] = ffma2(xd[v],     w2, acc[0][k]);
                        acc[1][k] = ffma2(xd[v + 1], w2, acc[1][k]);
                    }
                }
            }
        }
        int y = y0 + yy;
#pragma unroll
        for (int p = 0; p < 2; p++) {
            int x = x0 + p;
#pragma unroll
            for (int k = 0; k < 5; k++) {
                float lo, hi; upk2(acc[p][k], lo, hi);
                ts[2 * k] += lo;     tq[2 * k] += lo * lo;
                ts[2 * k + 1] += hi; tq[2 * k + 1] += hi * hi;
                size_t o0 = ((((size_t)b * 10 + 2 * k) * 4 + r) * 24 + y) * 24 + x;
                out[o0] = lo;
                out[o0 + (size_t)2304] = hi;
            }
        }
    }
#pragma unroll
    for (int o = 0; o < 10; o++) {
        float s = warpsum(ts[o]);
        float qv = warpsum(tq[o]);
        if ((tid & 31) == 0) { atomicAdd(&bsum[o], s); atomicAdd(&bsq[o], qv); }
    }
    __syncthreads();
    if (tid < 10) {
        atomicAdd(&g_sum[10 + tid], (double)bsum[tid]);
        atomicAdd(&g_sq[10 + tid], (double)bsq[tid]);
    }
}

// ---------------- fused layer ----------------
template <int H, int NT, int PXCH, int GIMG, bool LPOOL>
__global__ void __launch_bounds__(NT, 2) fusedgg(const float* __restrict__ in,
                                                 float* __restrict__ out,
                                                 int wlayer, int alayer, int statsIdx,
                                                 int bnIdx, const float* __restrict__ bng,
                                                 const float* __restrict__ bnb, float invN) {
    constexpr int HO = H - 2, WO = H - 2, HP = (H + 3) & ~3;
    constexpr int H2 = H * H, PLANE = H * HP;
    constexpr int NQ = (WO + PXCH - 1) / PXCH;
    constexpr int TASKS = GIMG * 4 * HO * NQ;
    constexpr int PW4R = ((H + 6) + 3) & ~3;
    constexpr int PW4 = (PW4R % 16 == 0) ? PW4R + 4 : PW4R;
    constexpr int TILE = 8 * PW4 * PW4;
    constexpr int NQA = (H + 3) / 4;
    extern __shared__ float sm[];
    float* sx = sm;
    float* sw = sm + GIMG * 40 * PLANE + 8;
    float* tile = sw;
    float* wa_s = sw + TILE + 16;
    float* att_s = wa_s + 1568;
    __shared__ float bsum[10], bsq[10], sc[10], sh[10];
    int grp = blockIdx.x, tid = threadIdx.x;
    if (tid < 10) { bsum[tid] = 0.f; bsq[tid] = 0.f; }
    bn_smem(tid, bnIdx, bng, bnb, invN, sc, sh);
    if (tid < 8) sx[GIMG * 40 * PLANE + tid] = 0.f;
    __syncthreads();

    for (int li = 0; li < GIMG; li++) {
        int b = grp * GIMG + li;
        if (LPOOL) {
            const float* inb = in + (size_t)b * 40 * 576;
            for (int idx = tid; idx < 40 * H2; idx += NT) {
                int is = idx / H2, pos = idx - is * H2;
                int y = pos / H, x = pos - y * H;
                const float* p = inb + (size_t)is * 576 + (2 * y) * 24 + 2 * x;
                float2 A = *(const float2*)p;
                float2 Bv = *(const float2*)(p + 24);
                float s = sc[is >> 2], t = sh[is >> 2];
                float v0 = fmaf(A.x, s, t), v1 = fmaf(A.y, s, t);
                float v2 = fmaf(Bv.x, s, t), v3 = fmaf(Bv.y, s, t);
                float v = fmaxf(fmaxf(v0, v1), fmaxf(v2, v3));
                v = v > 0.f ? v : 0.f;
                sx[((li * 40 + is) * H + y) * HP + x] = v;
            }
        } else {
            const float* inb = in + (size_t)b * 40 * H2;
            for (int idx = tid; idx < 40 * H2; idx += NT) {
                int is = idx / H2, pos = idx - is * H2;
                int y = pos / H, x = pos - y * H;
                float v = inb[idx];
                v = fmaf(v, sc[is >> 2], sh[is >> 2]);
                v = v > 0.f ? v : 0.f;
                sx[((li * 40 + is) * H + y) * HP + x] = v;
            }
        }
    }
    for (int i = tid; i < 1568; i += NT) wa_s[i] = g_wa[alayer * 1568 + i];
    __syncthreads();

    for (int li = 0; li < GIMG; li++) {
        for (int i = tid; i < TILE; i += NT) tile[i] = 0.f;
        __syncthreads();
        for (int idx = tid; idx < 4 * H2; idx += NT) {
            int s = idx / H2, pos = idx - s * H2;
            int y = pos / H, x = pos - y * H;
            float sum = 0.f, mx = -3.4e38f;
#pragma unroll
            for (int c = 0; c < 10; c++) {
                float v = sx[((li * 40 + c * 4 + s) * H + y) * HP + x];
                sum += v; mx = fmaxf(mx, v);
            }
            tile[(s * PW4 + y + 3) * PW4 + x + 3] = sum * 0.1f;
            tile[((4 + s) * PW4 + y + 3) * PW4 + x + 3] = mx;
        }
        __syncthreads();
        for (int t = tid; t < 4 * NQA * H; t += NT) {
            int q = t % NQA; int y = (t / NQA) % H; int r = t / (NQA * H);
            int x0 = q * 4;
            float a0 = 0.f, a1 = 0.f, a2 = 0.f, a3 = 0.f;
            const float* wb0 = &wa_s[r * 392];
#pragma unroll
            for (int js = 0; js < 8; js++) {
#pragma unroll
                for (int u = 0; u < 7; u++) {
                    const float* rowp = &tile[(js * PW4 + y + u) * PW4 + x0];
                    float4 A = *(const float4*)rowp;
                    float4 Bv = *(const float4*)(rowp + 4);
                    float2 Cv = *(const float2*)(rowp + 8);
                    float rr[10] = {A.x, A.y, A.z, A.w, Bv.x, Bv.y, Bv.z, Bv.w, Cv.x, Cv.y};
                    const float* wb = &wb0[js * 49 + u * 7];
#pragma unroll
                    for (int v = 0; v < 7; v++) {
                        float w = wb[v];
                        a0 = fmaf(rr[v], w, a0);
                        a1 = fmaf(rr[v + 1], w, a1);
                        a2 = fmaf(rr[v + 2], w, a2);
                        a3 = fmaf(rr[v + 3], w, a3);
                    }
                }
            }
            float* ob = &att_s[(li * 4 + r) * H2 + y * H];
            if (x0 < H)     ob[x0]     = 1.f / (1.f + expf(-a0));
            if (x0 + 1 < H) ob[x0 + 1] = 1.f / (1.f + expf(-a1));
            if (x0 + 2 < H) ob[x0 + 2] = 1.f / (1.f + expf(-a2));
            if (x0 + 3 < H) ob[x0 + 3] = 1.f / (1.f + expf(-a3));
        }
        __syncthreads();
    }

    for (int li = 0; li < GIMG; li++)
        for (int idx = tid; idx < 40 * H2; idx += NT) {
            int is = idx / H2, pos = idx - is * H2;
            int y = pos / H, x = pos - y * H;
            sx[((li * 40 + is) * H + y) * HP + x] *= att_s[(li * 4 + (is & 3)) * H2 + pos];
        }
    __syncthreads();
    {
        const float4* wg = (const float4*)&g_wc[wlayer * 14400];
        float4* swv = (float4*)sw;
        for (int i = tid; i < 3600; i += NT) swv[i] = wg[i];
    }
    __syncthreads();

    float ts[10], tq[10];
#pragma unroll
    for (int o = 0; o < 10; o++) { ts[o] = 0.f; tq[o] = 0.f; }

    for (int task = tid; task < TASKS; task += NT) {
        int q = task % NQ;
        int t2 = task / NQ;
        int y = t2 % HO; t2 /= HO;
        int r = t2 & 3; int li = t2 >> 2;
        int x0 = q * PXCH;
        u64 acc[PXCH][5];
#pragma unroll
        for (int p = 0; p < PXCH; p++)
#pragma unroll
            for (int k = 0; k < 5; k++) acc[p][k] = 0ull;
        const float* wr = &sw[r * 3600];
        const float* xb0 = &sx[(li * 40 * H + y) * HP + x0];
        for (int is = 0; is < 40; is++) {
            const float* xb = xb0 + is * PLANE;
            const float* wb = wr + is * 90;
#pragma unroll
            for (int u = 0; u < 3; u++) {
                u64 xd[PXCH + 2];
                if (PXCH == 4) {
                    float4 v4 = *(const float4*)(xb + u * HP);
                    float2 v2 = *(const float2*)(xb + u * HP + 4);
                    xd[0] = pk2(v4.x, v4.x); xd[1] = pk2(v4.y, v4.y);
                    xd[2] = pk2(v4.z, v4.z); xd[3] = pk2(v4.w, v4.w);
                    xd[4] = pk2(v2.x, v2.x); xd[5] = pk2(v2.y, v2.y);
                } else {
                    float2 vA = *(const float2*)(xb + u * HP);
                    float2 vB = *(const float2*)(xb + u * HP + 2);
                    xd[0] = pk2(vA.x, vA.x); xd[1] = pk2(vA.y, vA.y);
                    xd[2] = pk2(vB.x, vB.x); xd[3] = pk2(vB.y, vB.y);
                }
#pragma unroll
                for (int v = 0; v < 3; v++) {
                    const u64* wp = (const u64*)(wb + u * 30 + v * 10);
#pragma unroll
                    for (int k = 0; k < 5; k++) {
                        u64 w2 = wp[k];
#pragma unroll
                        for (int p = 0; p < PXCH; p++)
                            acc[p][k] = ffma2(xd[v + p], w2, acc[p][k]);
                    }
                }
            }
        }
        int b = grp * GIMG + li;
#pragma unroll
        for (int p = 0; p < PXCH; p++) {
            int x = x0 + p;
            if (x < WO) {
#pragma unroll
                for (int k = 0; k < 5; k++) {
                    float lo, hi; upk2(acc[p][k], lo, hi);
                    ts[2 * k] += lo;     tq[2 * k] += lo * lo;
                    ts[2 * k + 1] += hi; tq[2 * k + 1] += hi * hi;
                    size_t o0 = ((((size_t)b * 10 + 2 * k) * 4 + r) * HO + y) * WO + x;
                    out[o0] = lo;
                    out[o0 + (size_t)4 * HO * WO] = hi;
                }
            }
        }
    }
#pragma unroll
    for (int o = 0; o < 10; o++) {
        float s = warpsum(ts[o]);
        float qv = warpsum(tq[o]);
        if ((tid & 31) == 0) { atomicAdd(&bsum[o], s); atomicAdd(&bsq[o], qv); }
    }
    __syncthreads();
    if (tid < 10) {
        atomicAdd(&g_sum[statsIdx * 10 + tid], (double)bsum[tid]);
        atomicAdd(&g_sq[statsIdx * 10 + tid], (double)bsq[tid]);
    }
}

// ---------------- layer 7 fused ----------------
__global__ void __launch_bounds__(64) conv7k(const float* __restrict__ in,
                                             float* __restrict__ outp,
                                             const float* __restrict__ bng,
                                             const float* __restrict__ bnb, float invN) {
    __shared__ float sx[640], yv[40], sc[10], sh[10];
    __shared__ float tile[8 * 12 * 12 + 16];
    __shared__ float wa_s[1568];
    __shared__ float att_s[64];
    int b = blockIdx.x, tid = threadIdx.x;
    bn_smem(tid, 5, bng, bnb, invN, sc, sh);
    for (int i = tid; i < 8 * 144 + 16; i += 64) tile[i] = 0.f;
    for (int i = tid; i < 1568; i += 64) wa_s[i] = g_wa[5 * 1568 + i];
    __syncthreads();
    for (int idx = tid; idx < 640; idx += 64) {
        int c = idx >> 6;
        float v = in[(size_t)b * 640 + idx];
        v = fmaf(v, sc[c], sh[c]);
        sx[idx] = v > 0.f ? v : 0.f;
    }
    __syncthreads();
    if (tid < 64) {
        int s = tid / 16, pos = tid & 15;
        int y = pos >> 2, x = pos & 3;
        float sum = 0.f, mx = -3.4e38f;
#pragma unroll
        for (int c = 0; c < 10; c++) {
            float v = sx[(c * 4 + s) * 16 + pos];
            sum += v; mx = fmaxf(mx, v);
        }
        tile[(s * 12 + y + 3) * 12 + x + 3] = sum * 0.1f;
        tile[((4 + s) * 12 + y + 3) * 12 + x + 3] = mx;
    }
    __syncthreads();
    if (tid < 64) {
        int r = tid / 16, pos = tid & 15;
        int y = pos >> 2, x = pos & 3;
        float acc = 0.f;
        const float* wb0 = &wa_s[r * 392];
#pragma unroll
        for (int js = 0; js < 8; js++)
#pragma unroll
            for (int u = 0; u < 7; u++) {
                const float* rowp = &tile[(js * 12 + y + u) * 12 + x];
                const float* wb = &wb0[js * 49 + u * 7];
#pragma unroll
                for (int v = 0; v < 7; v++) acc = fmaf(rowp[v], wb[v], acc);
            }
        att_s[r * 16 + pos] = 1.f / (1.f + expf(-acc));
    }
    __syncthreads();
    for (int idx = tid; idx < 640; idx += 64) {
        int is = (idx >> 4) & 3;
        sx[idx] *= att_s[is * 16 + (idx & 15)];
    }
    __syncthreads();
    if (tid < 40) {
        int r = tid / 10, o = tid % 10;
        float acc = 0.f;
        for (int is = 0; is < 40; is++) {
#pragma unroll
            for (int t = 0; t < 16; t++)
                acc = fmaf(sx[is * 16 + t], __ldg(&g_wc7[((r * 40 + is) * 16 + t) * 10 + o]), acc);
        }
        yv[r * 10 + o] = acc;
    }
    __syncthreads();
    if (tid < 10) {
        float m = yv[tid];
        for (int r = 1; r < 4; r++) m = fmaxf(m, yv[r * 10 + tid]);
        outp[(size_t)b * 10 + tid] = m;
    }
}

// ---------------- launch ----------------
extern "C" void kernel_launch(void* const* d_in, const int* in_sizes, int n_in,
                              void* d_out, int out_size) {
    const float* x  = (const float*)d_in[0];
    const float* c1 = (const float*)d_in[1];
    const float* a1 = (const float*)d_in[2];
    const float* c2 = (const float*)d_in[3];
    const float* a2 = (const float*)d_in[4];
    const float* c3 = (const float*)d_in[5];
    const float* a3 = (const float*)d_in[6];
    const float* c4 = (const float*)d_in[7];
    const float* a4 = (const float*)d_in[8];
    const float* c5 = (const float*)d_in[9];
    const float* a5 = (const float*)d_in[10];
    const float* c6 = (const float*)d_in[11];
    const float* a6 = (const float*)d_in[12];
    const float* c7 = (const float*)d_in[13];
    const float* a7 = (const float*)d_in[14];
    const float* bn_g[6] = {(const float*)d_in[15], (const float*)d_in[17], (const float*)d_in[19],
                            (const float*)d_in[21], (const float*)d_in[23], (const float*)d_in[25]};
    const float* bn_b[6] = {(const float*)d_in[16], (const float*)d_in[18], (const float*)d_in[20],
                            (const float*)d_in[22], (const float*)d_in[24], (const float*)d_in[26]};
    float* out = (float*)d_out;

    int B = in_sizes[0] / 784;
    if (B > BMAX) B = BMAX;

    float *b0, *b1;
    cudaGetSymbolAddress((void**)&b0, g_buf0);
    cudaGetSymbolAddress((void**)&b1, g_buf1);

    const int SMA2 = (3136 + 2 * 9248) * 4;
    const int SML2 = (11208 + 14400) * 4;
    const int SM3 = (2 * 40 * 12 * 12 + 8 + 14400) * 4;
    const int SM4 = (2 * 40 * 10 * 12 + 8 + 14400) * 4;
    const int SM5 = (4 * 40 * 8 * 8 + 8 + 14400) * 4;
    const int SM6 = (4 * 40 * 6 * 8 + 8 + 14400) * 4;
    cudaFuncSetAttribute((const void*)attk2,  cudaFuncAttributeMaxDynamicSharedMemorySize, SMA2);
    cudaFuncSetAttribute((const void*)convL2, cudaFuncAttributeMaxDynamicSharedMemorySize, SML2);
    cudaFuncSetAttribute((const void*)fusedgg<12, 256, 4, 2, true>,  cudaFuncAttributeMaxDynamicSharedMemorySize, SM3);
    cudaFuncSetAttribute((const void*)fusedgg<10, 256, 2, 2, false>, cudaFuncAttributeMaxDynamicSharedMemorySize, SM4);
    cudaFuncSetAttribute((const void*)fusedgg<8, 288, 2, 4, false>,  cudaFuncAttributeMaxDynamicSharedMemorySize, SM5);
    cudaFuncSetAttribute((const void*)fusedgg<6, 128, 2, 4, false>,  cudaFuncAttributeMaxDynamicSharedMemorySize, SM6);

    prepk<<<64, 128>>>(c1, c2, c3, c4, c5, c6, c7, a1, a2, a3, a4, a5, a6, a7);

    l1k<<<B, 256>>>(x);

    float invN0 = 1.f / (float)(B * 4 * 676);
    attk2<<<B / 2, 256, SMA2>>>(bn_g[0], bn_b[0], invN0);
    convL2<<<B * 3, 384, SML2>>>(b0, b1, bn_g[0], bn_b[0], invN0);

    fusedgg<12, 256, 4, 2, true><<<B / 2, 256, SM3>>>(b1, b0, 1, 1, 2, 1, bn_g[1], bn_b[1], 1.f / (float)(B * 4 * 576));
    fusedgg<10, 256, 2, 2, false><<<B / 2, 256, SM4>>>(b0, b1, 2, 2, 3, 2, bn_g[2], bn_b[2], 1.f / (float)(B * 4 * 100));
    fusedgg<8, 288, 2, 4, false><<<B / 4, 288, SM5>>>(b1, b0, 3, 3, 4, 3, bn_g[3], bn_b[3], 1.f / (float)(B * 4 * 64));
    fusedgg<6, 128, 2, 4, false><<<B / 4, 128, SM6>>>(b0, b1, 4, 4, 5, 4, bn_g[4], bn_b[4], 1.f / (float)(B * 4 * 36));
    conv7k<<<B, 64>>>(b1, out, bn_g[5], bn_b[5], 1.f / (float)(B * 4 * 16));
}